// round 2
// baseline (speedup 1.0000x reference)
#include <cuda_runtime.h>
#include <cuda_bf16.h>
#include <stdint.h>

#define BB   8192
#define GG   900
#define NC   10
#define HID  128
#define ADIM 128
#define ZDIM 64
#define GFD  16
#define RHID 64
#define NT   64

#define CHUNK 8
#define ROWB  (NC*HID*2)            /* 2560 bytes of bf16 candidate rows per cell */
#define STAGE_BYTES (CHUNK*ROWB)    /* 20480 */
#define COLORS_OFF  (2*STAGE_BYTES) /* 40960 */
#define ENC1_SMEM   (COLORS_OFF + 64*GG)   /* 40960 + 57600 = 98560 */

#define REST_SMEM_FLOATS 21504      /* 86016 bytes */

static __device__ __nv_bfloat16 g_w1b[GG*NC*HID]; // bf16 copy of enc_w1
static __device__ unsigned char g_colors[BB*GG];  // grid as u8
static __device__ float         g_h1[BB*HID];     // encoder layer-1 output
static __device__ int           g_is64;

__device__ __forceinline__ float gelu_f(float x){
    return 0.5f * x * (1.0f + erff(x * 0.7071067811865476f));
}

// ---------------------------------------------------------------------------
// Detect whether grid buffer is int64 (odd int32 words all zero) or int32.
// ---------------------------------------------------------------------------
__global__ void k_detect(const unsigned int* __restrict__ g32){
    unsigned v = 0;
    if (threadIdx.x < 16) v = g32[2*threadIdx.x + 1];
    unsigned any = __ballot_sync(0xffffffffu, v != 0u);
    if (threadIdx.x == 0) g_is64 = (any == 0u) ? 1 : 0;
}

// ---------------------------------------------------------------------------
// Convert enc_w1 -> bf16 blob; convert grid -> u8 colors.
// ---------------------------------------------------------------------------
__global__ void k_prep(const float* __restrict__ w1, const unsigned int* __restrict__ g32){
    const int stride = gridDim.x * blockDim.x;
    const int t = blockIdx.x * blockDim.x + threadIdx.x;
    for (int i = t; i < GG*NC*HID; i += stride)
        g_w1b[i] = __float2bfloat16(w1[i]);
    const int is64 = g_is64;
    if (is64){
        for (int i = t; i < BB*GG; i += stride)
            g_colors[i] = (unsigned char)g32[2*i];
    } else {
        for (int i = t; i < BB*GG; i += stride)
            g_colors[i] = (unsigned char)g32[i];
    }
}

// ---------------------------------------------------------------------------
// Encoder layer 1: h1[b][j] = gelu(b1[j] + sum_cell w1[cell*10+color, j])
// Block: 512 threads, 64 batch elements. Candidate rows (10 per cell) staged
// in SMEM via cp.async double-buffered 8-cell chunks.
// Thread t: q = t&31 owns hid [4q,4q+3]; warp w = t>>5 owns batch w*4..w*4+3.
// ---------------------------------------------------------------------------
__global__ __launch_bounds__(512) void k_enc1(const float* __restrict__ b1){
    extern __shared__ char smem[];
    unsigned char* colors = (unsigned char*)(smem + COLORS_OFF);
    const int tid = threadIdx.x;
    const int q = tid & 31, w = tid >> 5;
    const int bblock = blockIdx.x * 64;

    // load 64x900 color tile, transposed to [cell][64]
    for (int idx = tid; idx < 64*GG; idx += 512){
        int bl = idx / GG;
        int cell = idx - bl*GG;
        colors[cell*64 + bl] = g_colors[(bblock + bl)*GG + cell];
    }

    const unsigned smem_s = (unsigned)__cvta_generic_to_shared(smem);
    const char* wsrc = (const char*)g_w1b;

    auto issue = [&](int s){
        int base = s * CHUNK;
        if (base < GG){
            int cells = min(CHUNK, GG - base);
            int bytes = cells * ROWB;
            unsigned dbase = smem_s + (s & 1) * STAGE_BYTES;
            const char* sbase = wsrc + (size_t)base * ROWB;
            for (int off = tid*16; off < bytes; off += 512*16){
                asm volatile("cp.async.ca.shared.global [%0], [%1], 16;"
                             :: "r"(dbase + off), "l"(sbase + off));
            }
        }
        asm volatile("cp.async.commit_group;");
    };

    float acc[4][4];
    #pragma unroll
    for (int ib = 0; ib < 4; ib++)
        #pragma unroll
        for (int j = 0; j < 4; j++) acc[ib][j] = 0.0f;

    issue(0); issue(1);
    const int NST = (GG + CHUNK - 1) / CHUNK;

    for (int s = 0; s < NST; s++){
        asm volatile("cp.async.wait_group 1;" ::: "memory");
        __syncthreads();
        const __nv_bfloat16* rbuf = (const __nv_bfloat16*)(smem + (s & 1) * STAGE_BYTES);
        const int cbase = s * CHUNK;
        const int cells = min(CHUNK, GG - cbase);

        auto body = [&](int ci){
            unsigned c4 = *(const unsigned*)(colors + (cbase + ci)*64 + w*4);
            #pragma unroll
            for (int ib = 0; ib < 4; ib++){
                int c = (c4 >> (8*ib)) & 0xFF;
                uint2 v = *(const uint2*)(rbuf + (ci*NC + c)*HID + q*4);
                acc[ib][0] += __uint_as_float(v.x << 16);
                acc[ib][1] += __uint_as_float(v.x & 0xFFFF0000u);
                acc[ib][2] += __uint_as_float(v.y << 16);
                acc[ib][3] += __uint_as_float(v.y & 0xFFFF0000u);
            }
        };
        if (cells == CHUNK){
            #pragma unroll
            for (int ci = 0; ci < CHUNK; ci++) body(ci);
        } else {
            for (int ci = 0; ci < cells; ci++) body(ci);
        }
        __syncthreads();
        issue(s + 2);
    }

    float4 bv = *(const float4*)(b1 + q*4);
    #pragma unroll
    for (int ib = 0; ib < 4; ib++){
        int bg = bblock + w*4 + ib;
        float4 o;
        o.x = gelu_f(acc[ib][0] + bv.x);
        o.y = gelu_f(acc[ib][1] + bv.y);
        o.z = gelu_f(acc[ib][2] + bv.z);
        o.w = gelu_f(acc[ib][3] + bv.w);
        *(float4*)(g_h1 + (size_t)bg*HID + q*4) = o;
    }
}

// ---------------------------------------------------------------------------
// Rest of the network: fully warp-local (warp owns 4 batch elements; SMEM
// activations, broadcast reads; weights via coalesced LDG, L1/L2 resident).
// ---------------------------------------------------------------------------
template<int I, int O, bool ACT>
__device__ __forceinline__ void dense(const float* __restrict__ Wg,
                                      const float* __restrict__ Bg,
                                      const float* in_s, float* out_s,
                                      int q, int w){
    constexpr int K = O / 32;
    float acc[4][K];
    #pragma unroll
    for (int k = 0; k < K; k++){
        float bvv = __ldg(Bg + q + 32*k);
        #pragma unroll
        for (int ib = 0; ib < 4; ib++) acc[ib][k] = bvv;
    }
    const float* i0 = in_s + (w*4 + 0)*I;
    const float* i1 = in_s + (w*4 + 1)*I;
    const float* i2 = in_s + (w*4 + 2)*I;
    const float* i3 = in_s + (w*4 + 3)*I;
    #pragma unroll 4
    for (int i = 0; i < I; i++){
        float wv[K];
        #pragma unroll
        for (int k = 0; k < K; k++) wv[k] = __ldg(Wg + i*O + q + 32*k);
        float a0 = i0[i], a1 = i1[i], a2 = i2[i], a3 = i3[i];
        #pragma unroll
        for (int k = 0; k < K; k++){
            acc[0][k] += a0 * wv[k];
            acc[1][k] += a1 * wv[k];
            acc[2][k] += a2 * wv[k];
            acc[3][k] += a3 * wv[k];
        }
    }
    #pragma unroll
    for (int k = 0; k < K; k++){
        #pragma unroll
        for (int ib = 0; ib < 4; ib++){
            float v = acc[ib][k];
            if (ACT) v = gelu_f(v);
            out_s[(w*4 + ib)*O + q + 32*k] = v;
        }
    }
    __syncwarp();
}

__global__ __launch_bounds__(256) void k_rest(
    const float* __restrict__ gfeat, const float* __restrict__ gum,
    const float* __restrict__ enc_w2, const float* __restrict__ enc_b2,
    const float* __restrict__ wy,     const float* __restrict__ by,
    const float* __restrict__ wz,     const float* __restrict__ bz,
    const float* __restrict__ rz_w1,  const float* __restrict__ rz_b1,
    const float* __restrict__ rz_w2,  const float* __restrict__ rz_b2,
    const float* __restrict__ ry_w1,  const float* __restrict__ ry_b1,
    const float* __restrict__ ry_w2,  const float* __restrict__ ry_b2,
    const float* __restrict__ sel_w1, const float* __restrict__ sel_b1,
    const float* __restrict__ sel_w2, const float* __restrict__ sel_b2,
    float* __restrict__ out)
{
    extern __shared__ float sm[];
    // Layout (floats):
    //   scat : [0,      6656)   32*208  — also used as initial h1 staging (32*128 fits)
    //   sh2  : [6656,  10752)   32*128  — h2, later logits (stride 64)
    //   sy   : [10752, 14848)   32*128
    //   sz   : [14848, 16896)   32*64
    //   sgf  : [16896, 17408)   32*16
    //   st   : [17408, 19456)   32*64
    float* scat = sm;
    float* sh2  = sm + 6656;
    float* sy   = sm + 10752;
    float* sz   = sm + 14848;
    float* sgf  = sm + 16896;
    float* st   = sm + 17408;
    const int tid = threadIdx.x, q = tid & 31, w = tid >> 5;
    const int b0 = blockIdx.x * 32;
    const int r0 = w*4;

    // Stage h1 into scat region, row-stride 128 (warp-local consumption after sync)
    for (int idx = tid; idx < 32*128; idx += 256) scat[idx] = g_h1[(size_t)b0*128 + idx];
    for (int idx = tid; idx < 32*16;  idx += 256) sgf[idx]  = gfeat[(size_t)b0*16 + idx];
    __syncthreads();

    dense<128,128,true >(enc_w2, enc_b2, scat, sh2, q, w);
    dense<128,128,false>(wy, by, sh2, sy, q, w);
    dense<128, 64,false>(wz, bz, sh2, sz, q, w);
    __syncwarp();   // scat (h1 staging) free for reuse below — warp-local from here on

    for (int cyc = 0; cyc < 3; cyc++){
        // cat_z = [y, z, gf]
        for (int idx = q; idx < 4*208; idx += 32){
            int r = idx / 208, i = idx - r*208;
            float v;
            if (i < 128)      v = sy [(r0+r)*128 + i];
            else if (i < 192) v = sz [(r0+r)*64  + (i-128)];
            else              v = sgf[(r0+r)*16  + (i-192)];
            scat[(r0+r)*208 + i] = v;
        }
        __syncwarp();
        dense<208,64,true >(rz_w1, rz_b1, scat, st, q, w);
        dense< 64,64,false>(rz_w2, rz_b2, st,   sz, q, w);
        // cat_y = [z_new, y, gf]
        for (int idx = q; idx < 4*208; idx += 32){
            int r = idx / 208, i = idx - r*208;
            float v;
            if (i < 64)       v = sz [(r0+r)*64  + i];
            else if (i < 192) v = sy [(r0+r)*128 + (i-64)];
            else              v = sgf[(r0+r)*16  + (i-192)];
            scat[(r0+r)*208 + i] = v;
        }
        __syncwarp();
        dense<208, 64,true >(ry_w1, ry_b1, scat, st, q, w);
        dense< 64,128,false>(ry_w2, ry_b2, st,   sy, q, w);
    }

    dense<128,64,true >(sel_w1, sel_b1, sy, st,  q, w);
    dense< 64,64,false>(sel_w2, sel_b2, st, sh2, q, w);  // logits, stride 64

    #pragma unroll
    for (int ib = 0; ib < 4; ib++){
        int bl = r0 + ib, bg = b0 + bl;
        float v0 = sh2[bl*64 + q]      + __ldg(gum + (size_t)bg*64 + q);
        float v1 = sh2[bl*64 + 32 + q] + __ldg(gum + (size_t)bg*64 + 32 + q);
        float m = fmaxf(v0, v1);
        #pragma unroll
        for (int o = 16; o; o >>= 1) m = fmaxf(m, __shfl_xor_sync(0xffffffffu, m, o));
        float e0 = expf(v0 - m), e1 = expf(v1 - m);
        float s = e0 + e1;
        #pragma unroll
        for (int o = 16; o; o >>= 1) s += __shfl_xor_sync(0xffffffffu, s, o);
        float inv = 1.0f / s;
        out[(size_t)bg*64 + q]      = e0 * inv;
        out[(size_t)bg*64 + 32 + q] = e1 * inv;
    }
}

// ---------------------------------------------------------------------------
extern "C" void kernel_launch(void* const* d_in, const int* in_sizes, int n_in,
                              void* d_out, int out_size){
    const unsigned int* grid32 = (const unsigned int*)d_in[0];
    const float* gfeat  = (const float*)d_in[1];
    const float* gum    = (const float*)d_in[2];
    const float* enc_w1 = (const float*)d_in[3];
    const float* enc_b1 = (const float*)d_in[4];
    const float* enc_w2 = (const float*)d_in[5];
    const float* enc_b2 = (const float*)d_in[6];
    const float* wy     = (const float*)d_in[7];
    const float* by     = (const float*)d_in[8];
    const float* wz     = (const float*)d_in[9];
    const float* bz     = (const float*)d_in[10];
    const float* rz_w1  = (const float*)d_in[11];
    const float* rz_b1  = (const float*)d_in[12];
    const float* rz_w2  = (const float*)d_in[13];
    const float* rz_b2  = (const float*)d_in[14];
    const float* ry_w1  = (const float*)d_in[15];
    const float* ry_b1  = (const float*)d_in[16];
    const float* ry_w2  = (const float*)d_in[17];
    const float* ry_b2  = (const float*)d_in[18];
    const float* sel_w1 = (const float*)d_in[19];
    const float* sel_b1 = (const float*)d_in[20];
    const float* sel_w2 = (const float*)d_in[21];
    const float* sel_b2 = (const float*)d_in[22];
    float* out = (float*)d_out;

    cudaFuncSetAttribute(k_enc1, cudaFuncAttributeMaxDynamicSharedMemorySize, ENC1_SMEM);
    cudaFuncSetAttribute(k_rest, cudaFuncAttributeMaxDynamicSharedMemorySize,
                         REST_SMEM_FLOATS*(int)sizeof(float));

    k_detect<<<1, 32>>>(grid32);
    k_prep<<<2048, 256>>>(enc_w1, grid32);
    k_enc1<<<BB/64, 512, ENC1_SMEM>>>(enc_b1);
    k_rest<<<BB/32, 256, REST_SMEM_FLOATS*sizeof(float)>>>(gfeat, gum,
        enc_w2, enc_b2, wy, by, wz, bz,
        rz_w1, rz_b1, rz_w2, rz_b2, ry_w1, ry_b1, ry_w2, ry_b2,
        sel_w1, sel_b1, sel_w2, sel_b2, out);
    (void)in_sizes; (void)n_in; (void)out_size;
}

// round 3
// speedup vs baseline: 1.0637x; 1.0637x over previous
#include <cuda_runtime.h>
#include <cuda_bf16.h>
#include <stdint.h>

#define BB   8192
#define GG   900
#define NC   10
#define HID  128
#define ADIM 128
#define ZDIM 64
#define GFD  16
#define RHID 64
#define NT   64

#define CHUNK 8
#define ROWB  (NC*HID*2)            /* 2560 bytes of bf16 candidate rows per cell */
#define STAGE_BYTES (CHUNK*ROWB)    /* 20480 */
#define COLORS_OFF  (2*STAGE_BYTES) /* 40960 */
#define ENC1_SMEM   (COLORS_OFF + 64*GG)   /* 98560 */

#define REST_SMEM_BYTES (12800*4)   /* 51200 */

typedef unsigned long long u64;

static __device__ __nv_bfloat16 g_w1b[GG*NC*HID]; // bf16 copy of enc_w1
static __device__ unsigned char g_colors[BB*GG];  // grid as u8
static __device__ float         g_h1[BB*HID];     // h1, PAIR-INTERLEAVED: [b/2][2*hid+(b&1)]
static __device__ int           g_is64;

__device__ __forceinline__ float gelu_f(float x){
    return 0.5f * x * (1.0f + erff(x * 0.7071067811865476f));
}

// ---- packed f32x2 helpers -------------------------------------------------
__device__ __forceinline__ u64 splat2(float v){
    u64 r; asm("mov.b64 %0, {%1, %1};" : "=l"(r) : "f"(v)); return r;
}
__device__ __forceinline__ u64 fma2(u64 a, u64 b, u64 c){
    u64 d; asm("fma.rn.f32x2 %0, %1, %2, %3;" : "=l"(d) : "l"(a), "l"(b), "l"(c)); return d;
}
__device__ __forceinline__ void unpack2(u64 v, float& lo, float& hi){
    asm("mov.b64 {%0, %1}, %2;" : "=f"(lo), "=f"(hi) : "l"(v));
}

// ---------------------------------------------------------------------------
__global__ void k_detect(const unsigned int* __restrict__ g32){
    unsigned v = 0;
    if (threadIdx.x < 16) v = g32[2*threadIdx.x + 1];
    unsigned any = __ballot_sync(0xffffffffu, v != 0u);
    if (threadIdx.x == 0) g_is64 = (any == 0u) ? 1 : 0;
}

__global__ void k_prep(const float* __restrict__ w1, const unsigned int* __restrict__ g32){
    const int stride = gridDim.x * blockDim.x;
    const int t = blockIdx.x * blockDim.x + threadIdx.x;
    for (int i = t; i < GG*NC*HID; i += stride)
        g_w1b[i] = __float2bfloat16(w1[i]);
    const int is64 = g_is64;
    if (is64){
        for (int i = t; i < BB*GG; i += stride)
            g_colors[i] = (unsigned char)g32[2*i];
    } else {
        for (int i = t; i < BB*GG; i += stride)
            g_colors[i] = (unsigned char)g32[i];
    }
}

// ---------------------------------------------------------------------------
// Encoder layer 1 (unchanged compute; h1 stored pair-interleaved).
// ---------------------------------------------------------------------------
__global__ __launch_bounds__(512) void k_enc1(const float* __restrict__ b1){
    extern __shared__ char smem[];
    unsigned char* colors = (unsigned char*)(smem + COLORS_OFF);
    const int tid = threadIdx.x;
    const int q = tid & 31, w = tid >> 5;
    const int bblock = blockIdx.x * 64;

    for (int idx = tid; idx < 64*GG; idx += 512){
        int bl = idx / GG;
        int cell = idx - bl*GG;
        colors[cell*64 + bl] = g_colors[(bblock + bl)*GG + cell];
    }

    const unsigned smem_s = (unsigned)__cvta_generic_to_shared(smem);
    const char* wsrc = (const char*)g_w1b;

    auto issue = [&](int s){
        int base = s * CHUNK;
        if (base < GG){
            int cells = min(CHUNK, GG - base);
            int bytes = cells * ROWB;
            unsigned dbase = smem_s + (s & 1) * STAGE_BYTES;
            const char* sbase = wsrc + (size_t)base * ROWB;
            for (int off = tid*16; off < bytes; off += 512*16){
                asm volatile("cp.async.ca.shared.global [%0], [%1], 16;"
                             :: "r"(dbase + off), "l"(sbase + off));
            }
        }
        asm volatile("cp.async.commit_group;");
    };

    float acc[4][4];
    #pragma unroll
    for (int ib = 0; ib < 4; ib++)
        #pragma unroll
        for (int j = 0; j < 4; j++) acc[ib][j] = 0.0f;

    issue(0); issue(1);
    const int NST = (GG + CHUNK - 1) / CHUNK;

    for (int s = 0; s < NST; s++){
        asm volatile("cp.async.wait_group 1;" ::: "memory");
        __syncthreads();
        const __nv_bfloat16* rbuf = (const __nv_bfloat16*)(smem + (s & 1) * STAGE_BYTES);
        const int cbase = s * CHUNK;
        const int cells = min(CHUNK, GG - cbase);

        auto body = [&](int ci){
            unsigned c4 = *(const unsigned*)(colors + (cbase + ci)*64 + w*4);
            #pragma unroll
            for (int ib = 0; ib < 4; ib++){
                int c = (c4 >> (8*ib)) & 0xFF;
                uint2 v = *(const uint2*)(rbuf + (ci*NC + c)*HID + q*4);
                acc[ib][0] += __uint_as_float(v.x << 16);
                acc[ib][1] += __uint_as_float(v.x & 0xFFFF0000u);
                acc[ib][2] += __uint_as_float(v.y << 16);
                acc[ib][3] += __uint_as_float(v.y & 0xFFFF0000u);
            }
        };
        if (cells == CHUNK){
            #pragma unroll
            for (int ci = 0; ci < CHUNK; ci++) body(ci);
        } else {
            for (int ci = 0; ci < cells; ci++) body(ci);
        }
        __syncthreads();
        issue(s + 2);
    }

    float bvv[4];
    { float4 bv = *(const float4*)(b1 + q*4); bvv[0]=bv.x; bvv[1]=bv.y; bvv[2]=bv.z; bvv[3]=bv.w; }
    #pragma unroll
    for (int ib = 0; ib < 4; ib += 2){
        int pair = (bblock + w*4 + ib) >> 1;
        #pragma unroll
        for (int j = 0; j < 4; j++){
            float lo = gelu_f(acc[ib  ][j] + bvv[j]);
            float hi = gelu_f(acc[ib+1][j] + bvv[j]);
            *(float2*)(g_h1 + (size_t)pair*256 + 2*(4*q + j)) = make_float2(lo, hi);
        }
    }
}

// ---------------------------------------------------------------------------
// k_rest v2: packed f32x2, 8 rows (4 pairs) per warp, 4 warps/block (32 rows).
// Activations pair-interleaved in SMEM: buf[pair][2*col + r], broadcast LDS.
// Weights: contiguous LDG.128/.64 per input row, splatted to {w,w}.
// ---------------------------------------------------------------------------
template<int C>
__device__ __forceinline__ void wload(float (&wv)[C], const float* __restrict__ p){
    if (C == 4){ float4 v = *(const float4*)p; wv[0]=v.x; wv[1]=v.y; wv[2]=v.z; wv[3]=v.w; }
    else       { float2 v = *(const float2*)p; wv[0]=v.x; wv[1]=v.y; }
}

template<int C, int LEN>
__device__ __forceinline__ void seg(u64 (&acc)[4][C], const float* __restrict__ Wg,
                                    const int O, const float* sp, const int pstr, const int q){
    #pragma unroll 2
    for (int i = 0; i < LEN; i += 2){
        ulonglong2 a0 = *(const ulonglong2*)(sp + 0*pstr + 2*i);
        ulonglong2 a1 = *(const ulonglong2*)(sp + 1*pstr + 2*i);
        ulonglong2 a2 = *(const ulonglong2*)(sp + 2*pstr + 2*i);
        ulonglong2 a3 = *(const ulonglong2*)(sp + 3*pstr + 2*i);
        float wv0[C], wv1[C];
        wload<C>(wv0, Wg + (size_t)i*O     + C*q);
        wload<C>(wv1, Wg + (size_t)(i+1)*O + C*q);
        #pragma unroll
        for (int c = 0; c < C; c++){
            u64 w0 = splat2(wv0[c]);
            acc[0][c] = fma2(a0.x, w0, acc[0][c]);
            acc[1][c] = fma2(a1.x, w0, acc[1][c]);
            acc[2][c] = fma2(a2.x, w0, acc[2][c]);
            acc[3][c] = fma2(a3.x, w0, acc[3][c]);
        }
        #pragma unroll
        for (int c = 0; c < C; c++){
            u64 w1 = splat2(wv1[c]);
            acc[0][c] = fma2(a0.y, w1, acc[0][c]);
            acc[1][c] = fma2(a1.y, w1, acc[1][c]);
            acc[2][c] = fma2(a2.y, w1, acc[2][c]);
            acc[3][c] = fma2(a3.y, w1, acc[3][c]);
        }
    }
}

template<int C>
__device__ __forceinline__ void initb(u64 (&acc)[4][C], const float* __restrict__ B, const int q){
    float bv[C]; wload<C>(bv, B + C*q);
    #pragma unroll
    for (int c = 0; c < C; c++){
        u64 s = splat2(bv[c]);
        #pragma unroll
        for (int p = 0; p < 4; p++) acc[p][c] = s;
    }
}

template<int C, bool ACT>
__device__ __forceinline__ void finish(u64 (&acc)[4][C], float* dp, const int pstr, const int q){
    #pragma unroll
    for (int p = 0; p < 4; p++)
        #pragma unroll
        for (int c = 0; c < C; c++){
            float lo, hi; unpack2(acc[p][c], lo, hi);
            if (ACT){ lo = gelu_f(lo); hi = gelu_f(hi); }
            *(float2*)(dp + p*pstr + 2*(C*q + c)) = make_float2(lo, hi);
        }
    __syncwarp();
}

__global__ __launch_bounds__(128) void k_rest(
    const float* __restrict__ gfeat, const float* __restrict__ gum,
    const float* __restrict__ enc_w2, const float* __restrict__ enc_b2,
    const float* __restrict__ wy,     const float* __restrict__ by,
    const float* __restrict__ wz,     const float* __restrict__ bz,
    const float* __restrict__ rz_w1,  const float* __restrict__ rz_b1,
    const float* __restrict__ rz_w2,  const float* __restrict__ rz_b2,
    const float* __restrict__ ry_w1,  const float* __restrict__ ry_b1,
    const float* __restrict__ ry_w2,  const float* __restrict__ ry_b2,
    const float* __restrict__ sel_w1, const float* __restrict__ sel_b1,
    const float* __restrict__ sel_w2, const float* __restrict__ sel_b2,
    float* __restrict__ out)
{
    extern __shared__ float sm[];
    // per-block: 16 pairs. widths (floats/pair): Y 256, L 256, Z 128, T 128, GF 32
    float* Y  = sm;            // 4096
    float* L  = sm + 4096;     // 4096
    float* Z  = sm + 8192;     // 2048
    float* T  = sm + 10240;    // 2048
    float* GF = sm + 12288;    // 512
    const int tid = threadIdx.x, q = tid & 31, w = tid >> 5;
    const int b0 = blockIdx.x * 32;

    // stage h1 (already pair-interleaved in global) straight into Y
    for (int idx = tid; idx < 4096; idx += 128)
        Y[idx] = g_h1[(size_t)(b0 >> 1)*256 + idx];
    // stage grid_features interleaved
    for (int idx = tid; idx < 32*16; idx += 128){
        int b = idx >> 4, i = idx & 15;
        GF[(b >> 1)*32 + 2*i + (b & 1)] = gfeat[(size_t)(b0 + b)*16 + i];
    }
    __syncthreads();

    float* Yw  = Y  + w*1024;
    float* Lw  = L  + w*1024;
    float* Zw  = Z  + w*512;
    float* Tw  = T  + w*512;
    float* GFw = GF + w*128;

    // h2 = gelu(h1 @ enc_w2 + b2)
    { u64 acc[4][4]; initb<4>(acc, enc_b2, q); seg<4,128>(acc, enc_w2, 128, Yw, 256, q); finish<4,true >(acc, Lw, 256, q); }
    // y = h2 @ wy + by
    { u64 acc[4][4]; initb<4>(acc, by, q);     seg<4,128>(acc, wy,     128, Lw, 256, q); finish<4,false>(acc, Yw, 256, q); }
    // z = h2 @ wz + bz
    { u64 acc[4][2]; initb<2>(acc, bz, q);     seg<2,128>(acc, wz,      64, Lw, 256, q); finish<2,false>(acc, Zw, 128, q); }

    #pragma unroll 1
    for (int cyc = 0; cyc < 3; cyc++){
        // t = gelu([y,z,gf] @ rz_w1 + b)
        { u64 acc[4][2]; initb<2>(acc, rz_b1, q);
          seg<2,128>(acc, rz_w1,          64, Yw,  256, q);
          seg<2, 64>(acc, rz_w1 + 128*64, 64, Zw,  128, q);
          seg<2, 16>(acc, rz_w1 + 192*64, 64, GFw,  32, q);
          finish<2,true>(acc, Tw, 128, q); }
        // z = t @ rz_w2 + b
        { u64 acc[4][2]; initb<2>(acc, rz_b2, q); seg<2,64>(acc, rz_w2, 64, Tw, 128, q); finish<2,false>(acc, Zw, 128, q); }
        // t = gelu([z,y,gf] @ ry_w1 + b)
        { u64 acc[4][2]; initb<2>(acc, ry_b1, q);
          seg<2, 64>(acc, ry_w1,          64, Zw,  128, q);
          seg<2,128>(acc, ry_w1 +  64*64, 64, Yw,  256, q);
          seg<2, 16>(acc, ry_w1 + 192*64, 64, GFw,  32, q);
          finish<2,true>(acc, Tw, 128, q); }
        // y = t @ ry_w2 + b
        { u64 acc[4][4]; initb<4>(acc, ry_b2, q); seg<4,64>(acc, ry_w2, 128, Tw, 128, q); finish<4,false>(acc, Yw, 256, q); }
    }

    // selector
    { u64 acc[4][2]; initb<2>(acc, sel_b1, q); seg<2,128>(acc, sel_w1, 64, Yw, 256, q); finish<2,true >(acc, Tw, 128, q); }
    { u64 acc[4][2]; initb<2>(acc, sel_b2, q); seg<2, 64>(acc, sel_w2, 64, Tw, 128, q); finish<2,false>(acc, Lw, 256, q); }

    // softmax((logits + gumbel)/1) per row; Lw holds logits interleaved
    #pragma unroll 1
    for (int rr = 0; rr < 8; rr++){
        int p = rr >> 1, r = rr & 1;
        int bg = b0 + 8*w + rr;
        float v0 = Lw[p*256 + 2*q        + r] + __ldg(gum + (size_t)bg*64 + q);
        float v1 = Lw[p*256 + 2*(q + 32) + r] + __ldg(gum + (size_t)bg*64 + 32 + q);
        float m = fmaxf(v0, v1);
        #pragma unroll
        for (int o = 16; o; o >>= 1) m = fmaxf(m, __shfl_xor_sync(0xffffffffu, m, o));
        float e0 = expf(v0 - m), e1 = expf(v1 - m);
        float s = e0 + e1;
        #pragma unroll
        for (int o = 16; o; o >>= 1) s += __shfl_xor_sync(0xffffffffu, s, o);
        float inv = 1.0f / s;
        out[(size_t)bg*64 + q]      = e0 * inv;
        out[(size_t)bg*64 + 32 + q] = e1 * inv;
    }
}

// ---------------------------------------------------------------------------
extern "C" void kernel_launch(void* const* d_in, const int* in_sizes, int n_in,
                              void* d_out, int out_size){
    const unsigned int* grid32 = (const unsigned int*)d_in[0];
    const float* gfeat  = (const float*)d_in[1];
    const float* gum    = (const float*)d_in[2];
    const float* enc_w1 = (const float*)d_in[3];
    const float* enc_b1 = (const float*)d_in[4];
    const float* enc_w2 = (const float*)d_in[5];
    const float* enc_b2 = (const float*)d_in[6];
    const float* wy     = (const float*)d_in[7];
    const float* by     = (const float*)d_in[8];
    const float* wz     = (const float*)d_in[9];
    const float* bz     = (const float*)d_in[10];
    const float* rz_w1  = (const float*)d_in[11];
    const float* rz_b1  = (const float*)d_in[12];
    const float* rz_w2  = (const float*)d_in[13];
    const float* rz_b2  = (const float*)d_in[14];
    const float* ry_w1  = (const float*)d_in[15];
    const float* ry_b1  = (const float*)d_in[16];
    const float* ry_w2  = (const float*)d_in[17];
    const float* ry_b2  = (const float*)d_in[18];
    const float* sel_w1 = (const float*)d_in[19];
    const float* sel_b1 = (const float*)d_in[20];
    const float* sel_w2 = (const float*)d_in[21];
    const float* sel_b2 = (const float*)d_in[22];
    float* out = (float*)d_out;

    cudaFuncSetAttribute(k_enc1, cudaFuncAttributeMaxDynamicSharedMemorySize, ENC1_SMEM);
    cudaFuncSetAttribute(k_rest, cudaFuncAttributeMaxDynamicSharedMemorySize, REST_SMEM_BYTES);

    k_detect<<<1, 32>>>(grid32);
    k_prep<<<2048, 256>>>(enc_w1, grid32);
    k_enc1<<<BB/64, 512, ENC1_SMEM>>>(enc_b1);
    k_rest<<<BB/32, 128, REST_SMEM_BYTES>>>(gfeat, gum,
        enc_w2, enc_b2, wy, by, wz, bz,
        rz_w1, rz_b1, rz_w2, rz_b2, ry_w1, ry_b1, ry_w2, ry_b2,
        sel_w1, sel_b1, sel_w2, sel_b2, out);
    (void)in_sizes; (void)n_in; (void)out_size;
}

// round 4
// speedup vs baseline: 1.1017x; 1.0357x over previous
#include <cuda_runtime.h>
#include <cuda_bf16.h>
#include <stdint.h>

#define BB   8192
#define GG   900
#define NC   10
#define HID  128
#define ADIM 128
#define ZDIM 64
#define GFD  16
#define RHID 64
#define NT   64

#define CHUNK 8
#define ROWB  (NC*HID*2)
#define STAGE_BYTES (CHUNK*ROWB)    /* 20480 */
#define COLORS_OFF  (2*STAGE_BYTES) /* 40960 */
#define ENC1_SMEM   (COLORS_OFF + 64*GG)   /* 98560 */

#define REST_SMEM_BYTES (12800*4)   /* 51200 */

/* bf16 weight blob offsets (elements) */
#define OFF_ENC2 0
#define OFF_WY   16384
#define OFF_WZ   32768
#define OFF_RZ1  40960
#define OFF_RZ2  54272
#define OFF_RY1  58368
#define OFF_RY2  71680
#define OFF_SEL1 79872
#define OFF_SEL2 88064
#define WR_TOTAL 92160

typedef unsigned long long u64;

static __device__ __nv_bfloat16 g_w1b[GG*NC*HID]; // bf16 copy of enc_w1
static __device__ __nv_bfloat16 g_wr[WR_TOTAL];   // bf16 copies of rest weights
static __device__ unsigned char g_colors[BB*GG];  // grid as u8
static __device__ float         g_h1[BB*HID];     // h1, pair-interleaved
static __device__ int           g_is64;

__device__ __forceinline__ float gelu_f(float x){
    return 0.5f * x * (1.0f + erff(x * 0.7071067811865476f));
}

// ---- packed f32x2 helpers -------------------------------------------------
__device__ __forceinline__ u64 splat2(float v){
    u64 r; asm("mov.b64 %0, {%1, %1};" : "=l"(r) : "f"(v)); return r;
}
__device__ __forceinline__ u64 fma2(u64 a, u64 b, u64 c){
    u64 d; asm("fma.rn.f32x2 %0, %1, %2, %3;" : "=l"(d) : "l"(a), "l"(b), "l"(c)); return d;
}
__device__ __forceinline__ void unpack2(u64 v, float& lo, float& hi){
    asm("mov.b64 {%0, %1}, %2;" : "=f"(lo), "=f"(hi) : "l"(v));
}

// ---------------------------------------------------------------------------
__global__ void k_detect(const unsigned int* __restrict__ g32){
    unsigned v = 0;
    if (threadIdx.x < 16) v = g32[2*threadIdx.x + 1];
    unsigned any = __ballot_sync(0xffffffffu, v != 0u);
    if (threadIdx.x == 0) g_is64 = (any == 0u) ? 1 : 0;
}

__device__ __forceinline__ void cvt_range(__nv_bfloat16* dst, const float* src, int n, int t, int stride){
    for (int i = t; i < n; i += stride) dst[i] = __float2bfloat16(src[i]);
}

__global__ void k_prep(const float* __restrict__ w1, const unsigned int* __restrict__ g32,
                       const float* __restrict__ enc_w2, const float* __restrict__ wy,
                       const float* __restrict__ wz,     const float* __restrict__ rz_w1,
                       const float* __restrict__ rz_w2,  const float* __restrict__ ry_w1,
                       const float* __restrict__ ry_w2,  const float* __restrict__ sel_w1,
                       const float* __restrict__ sel_w2){
    const int stride = gridDim.x * blockDim.x;
    const int t = blockIdx.x * blockDim.x + threadIdx.x;
    for (int i = t; i < GG*NC*HID; i += stride)
        g_w1b[i] = __float2bfloat16(w1[i]);
    cvt_range(g_wr + OFF_ENC2, enc_w2, 16384, t, stride);
    cvt_range(g_wr + OFF_WY,   wy,     16384, t, stride);
    cvt_range(g_wr + OFF_WZ,   wz,      8192, t, stride);
    cvt_range(g_wr + OFF_RZ1,  rz_w1,  13312, t, stride);
    cvt_range(g_wr + OFF_RZ2,  rz_w2,   4096, t, stride);
    cvt_range(g_wr + OFF_RY1,  ry_w1,  13312, t, stride);
    cvt_range(g_wr + OFF_RY2,  ry_w2,   8192, t, stride);
    cvt_range(g_wr + OFF_SEL1, sel_w1,  8192, t, stride);
    cvt_range(g_wr + OFF_SEL2, sel_w2,  4096, t, stride);
    const int is64 = g_is64;
    if (is64){
        for (int i = t; i < BB*GG; i += stride)
            g_colors[i] = (unsigned char)g32[2*i];
    } else {
        for (int i = t; i < BB*GG; i += stride)
            g_colors[i] = (unsigned char)g32[i];
    }
}

// ---------------------------------------------------------------------------
// Encoder layer 1 (unchanged; h1 stored pair-interleaved).
// ---------------------------------------------------------------------------
__global__ __launch_bounds__(512) void k_enc1(const float* __restrict__ b1){
    extern __shared__ char smem[];
    unsigned char* colors = (unsigned char*)(smem + COLORS_OFF);
    const int tid = threadIdx.x;
    const int q = tid & 31, w = tid >> 5;
    const int bblock = blockIdx.x * 64;

    for (int idx = tid; idx < 64*GG; idx += 512){
        int bl = idx / GG;
        int cell = idx - bl*GG;
        colors[cell*64 + bl] = g_colors[(bblock + bl)*GG + cell];
    }

    const unsigned smem_s = (unsigned)__cvta_generic_to_shared(smem);
    const char* wsrc = (const char*)g_w1b;

    auto issue = [&](int s){
        int base = s * CHUNK;
        if (base < GG){
            int cells = min(CHUNK, GG - base);
            int bytes = cells * ROWB;
            unsigned dbase = smem_s + (s & 1) * STAGE_BYTES;
            const char* sbase = wsrc + (size_t)base * ROWB;
            for (int off = tid*16; off < bytes; off += 512*16){
                asm volatile("cp.async.ca.shared.global [%0], [%1], 16;"
                             :: "r"(dbase + off), "l"(sbase + off));
            }
        }
        asm volatile("cp.async.commit_group;");
    };

    float acc[4][4];
    #pragma unroll
    for (int ib = 0; ib < 4; ib++)
        #pragma unroll
        for (int j = 0; j < 4; j++) acc[ib][j] = 0.0f;

    issue(0); issue(1);
    const int NST = (GG + CHUNK - 1) / CHUNK;

    for (int s = 0; s < NST; s++){
        asm volatile("cp.async.wait_group 1;" ::: "memory");
        __syncthreads();
        const __nv_bfloat16* rbuf = (const __nv_bfloat16*)(smem + (s & 1) * STAGE_BYTES);
        const int cbase = s * CHUNK;
        const int cells = min(CHUNK, GG - cbase);

        auto body = [&](int ci){
            unsigned c4 = *(const unsigned*)(colors + (cbase + ci)*64 + w*4);
            #pragma unroll
            for (int ib = 0; ib < 4; ib++){
                int c = (c4 >> (8*ib)) & 0xFF;
                uint2 v = *(const uint2*)(rbuf + (ci*NC + c)*HID + q*4);
                acc[ib][0] += __uint_as_float(v.x << 16);
                acc[ib][1] += __uint_as_float(v.x & 0xFFFF0000u);
                acc[ib][2] += __uint_as_float(v.y << 16);
                acc[ib][3] += __uint_as_float(v.y & 0xFFFF0000u);
            }
        };
        if (cells == CHUNK){
            #pragma unroll
            for (int ci = 0; ci < CHUNK; ci++) body(ci);
        } else {
            for (int ci = 0; ci < cells; ci++) body(ci);
        }
        __syncthreads();
        issue(s + 2);
    }

    float bvv[4];
    { float4 bv = *(const float4*)(b1 + q*4); bvv[0]=bv.x; bvv[1]=bv.y; bvv[2]=bv.z; bvv[3]=bv.w; }
    #pragma unroll
    for (int ib = 0; ib < 4; ib += 2){
        int pair = (bblock + w*4 + ib) >> 1;
        #pragma unroll
        for (int j = 0; j < 4; j++){
            float lo = gelu_f(acc[ib  ][j] + bvv[j]);
            float hi = gelu_f(acc[ib+1][j] + bvv[j]);
            *(float2*)(g_h1 + (size_t)pair*256 + 2*(4*q + j)) = make_float2(lo, hi);
        }
    }
}

// ---------------------------------------------------------------------------
// k_rest v3: packed f32x2, bf16 weights, software-pipelined inner loop.
// 8 rows (4 pairs) per warp, 4 warps/block, grid = BB/32.
// ---------------------------------------------------------------------------
__device__ __forceinline__ float blo(unsigned v){ return __uint_as_float(v << 16); }
__device__ __forceinline__ float bhi(unsigned v){ return __uint_as_float(v & 0xFFFF0000u); }

template<int C>
__device__ __forceinline__ void fma_row(u64 (&acc)[4][C], const unsigned (&wb)[C/2],
                                        const u64 a0, const u64 a1, const u64 a2, const u64 a3){
    #pragma unroll
    for (int c = 0; c < C; c++){
        unsigned v = wb[c >> 1];
        u64 ws = splat2((c & 1) ? bhi(v) : blo(v));
        acc[0][c] = fma2(a0, ws, acc[0][c]);
        acc[1][c] = fma2(a1, ws, acc[1][c]);
        acc[2][c] = fma2(a2, ws, acc[2][c]);
        acc[3][c] = fma2(a3, ws, acc[3][c]);
    }
}

// Wg: bf16 weights as u32 pairs, row stride Ow (u32 units). LEN >= 4, even.
template<int C, int LEN>
__device__ __forceinline__ void segb(u64 (&acc)[4][C], const unsigned* __restrict__ Wg,
                                     const int Ow, const float* sp, const int pstr, const int q){
    constexpr int CW = C/2;
    const unsigned* Wp = Wg + CW*q;
    unsigned w0[CW], w1[CW];
    u64 ax[4], ay[4];
    #pragma unroll
    for (int j = 0; j < CW; j++){ w0[j] = __ldg(Wp + j); w1[j] = __ldg(Wp + Ow + j); }
    #pragma unroll
    for (int p = 0; p < 4; p++){
        ulonglong2 t = *(const ulonglong2*)(sp + p*pstr);
        ax[p] = t.x; ay[p] = t.y;
    }
    #pragma unroll 2
    for (int i = 0; i < LEN - 2; i += 2){
        unsigned nw0[CW], nw1[CW];
        u64 nax[4], nay[4];
        #pragma unroll
        for (int j = 0; j < CW; j++){
            nw0[j] = __ldg(Wp + (i+2)*Ow + j);
            nw1[j] = __ldg(Wp + (i+3)*Ow + j);
        }
        #pragma unroll
        for (int p = 0; p < 4; p++){
            ulonglong2 t = *(const ulonglong2*)(sp + p*pstr + 2*(i+2));
            nax[p] = t.x; nay[p] = t.y;
        }
        fma_row<C>(acc, w0, ax[0], ax[1], ax[2], ax[3]);
        fma_row<C>(acc, w1, ay[0], ay[1], ay[2], ay[3]);
        #pragma unroll
        for (int j = 0; j < CW; j++){ w0[j] = nw0[j]; w1[j] = nw1[j]; }
        #pragma unroll
        for (int p = 0; p < 4; p++){ ax[p] = nax[p]; ay[p] = nay[p]; }
    }
    fma_row<C>(acc, w0, ax[0], ax[1], ax[2], ax[3]);
    fma_row<C>(acc, w1, ay[0], ay[1], ay[2], ay[3]);
}

template<int C>
__device__ __forceinline__ void wloadf(float (&wv)[C], const float* __restrict__ p){
    if (C == 4){ float4 v = *(const float4*)p; wv[0]=v.x; wv[1]=v.y; wv[2]=v.z; wv[3]=v.w; }
    else       { float2 v = *(const float2*)p; wv[0]=v.x; wv[1]=v.y; }
}

template<int C>
__device__ __forceinline__ void initb(u64 (&acc)[4][C], const float* __restrict__ B, const int q){
    float bv[C]; wloadf<C>(bv, B + C*q);
    #pragma unroll
    for (int c = 0; c < C; c++){
        u64 s = splat2(bv[c]);
        #pragma unroll
        for (int p = 0; p < 4; p++) acc[p][c] = s;
    }
}

template<int C, bool ACT>
__device__ __forceinline__ void finish(u64 (&acc)[4][C], float* dp, const int pstr, const int q){
    #pragma unroll
    for (int p = 0; p < 4; p++)
        #pragma unroll
        for (int c = 0; c < C; c++){
            float lo, hi; unpack2(acc[p][c], lo, hi);
            if (ACT){ lo = gelu_f(lo); hi = gelu_f(hi); }
            *(float2*)(dp + p*pstr + 2*(C*q + c)) = make_float2(lo, hi);
        }
    __syncwarp();
}

__global__ __launch_bounds__(128) void k_rest(
    const float* __restrict__ gfeat, const float* __restrict__ gum,
    const float* __restrict__ enc_b2, const float* __restrict__ by,
    const float* __restrict__ bz,     const float* __restrict__ rz_b1,
    const float* __restrict__ rz_b2,  const float* __restrict__ ry_b1,
    const float* __restrict__ ry_b2,  const float* __restrict__ sel_b1,
    const float* __restrict__ sel_b2,
    float* __restrict__ out)
{
    extern __shared__ float sm[];
    float* Y  = sm;            // 4096
    float* L  = sm + 4096;     // 4096
    float* Z  = sm + 8192;     // 2048
    float* T  = sm + 10240;    // 2048
    float* GF = sm + 12288;    // 512
    const int tid = threadIdx.x, q = tid & 31, w = tid >> 5;
    const int b0 = blockIdx.x * 32;
    const unsigned* WR = (const unsigned*)g_wr;

    for (int idx = tid; idx < 4096; idx += 128)
        Y[idx] = g_h1[(size_t)(b0 >> 1)*256 + idx];
    for (int idx = tid; idx < 32*16; idx += 128){
        int b = idx >> 4, i = idx & 15;
        GF[(b >> 1)*32 + 2*i + (b & 1)] = gfeat[(size_t)(b0 + b)*16 + i];
    }
    __syncthreads();

    float* Yw  = Y  + w*1024;
    float* Lw  = L  + w*1024;
    float* Zw  = Z  + w*512;
    float* Tw  = T  + w*512;
    float* GFw = GF + w*128;

    // h2 = gelu(h1 @ enc_w2 + b2)
    { u64 acc[4][4]; initb<4>(acc, enc_b2, q); segb<4,128>(acc, WR + OFF_ENC2/2, 64, Yw, 256, q); finish<4,true >(acc, Lw, 256, q); }
    // y = h2 @ wy + by
    { u64 acc[4][4]; initb<4>(acc, by, q);     segb<4,128>(acc, WR + OFF_WY/2,   64, Lw, 256, q); finish<4,false>(acc, Yw, 256, q); }
    // z = h2 @ wz + bz
    { u64 acc[4][2]; initb<2>(acc, bz, q);     segb<2,128>(acc, WR + OFF_WZ/2,   32, Lw, 256, q); finish<2,false>(acc, Zw, 128, q); }

    #pragma unroll 1
    for (int cyc = 0; cyc < 3; cyc++){
        { u64 acc[4][2]; initb<2>(acc, rz_b1, q);
          segb<2,128>(acc, WR + OFF_RZ1/2,             32, Yw,  256, q);
          segb<2, 64>(acc, WR + (OFF_RZ1 + 128*64)/2,  32, Zw,  128, q);
          segb<2, 16>(acc, WR + (OFF_RZ1 + 192*64)/2,  32, GFw,  32, q);
          finish<2,true>(acc, Tw, 128, q); }
        { u64 acc[4][2]; initb<2>(acc, rz_b2, q); segb<2,64>(acc, WR + OFF_RZ2/2, 32, Tw, 128, q); finish<2,false>(acc, Zw, 128, q); }
        { u64 acc[4][2]; initb<2>(acc, ry_b1, q);
          segb<2, 64>(acc, WR + OFF_RY1/2,             32, Zw,  128, q);
          segb<2,128>(acc, WR + (OFF_RY1 +  64*64)/2,  32, Yw,  256, q);
          segb<2, 16>(acc, WR + (OFF_RY1 + 192*64)/2,  32, GFw,  32, q);
          finish<2,true>(acc, Tw, 128, q); }
        { u64 acc[4][4]; initb<4>(acc, ry_b2, q); segb<4,64>(acc, WR + OFF_RY2/2, 64, Tw, 128, q); finish<4,false>(acc, Yw, 256, q); }
    }

    { u64 acc[4][2]; initb<2>(acc, sel_b1, q); segb<2,128>(acc, WR + OFF_SEL1/2, 32, Yw, 256, q); finish<2,true >(acc, Tw, 128, q); }
    { u64 acc[4][2]; initb<2>(acc, sel_b2, q); segb<2, 64>(acc, WR + OFF_SEL2/2, 32, Tw, 128, q); finish<2,false>(acc, Lw, 256, q); }

    #pragma unroll 1
    for (int rr = 0; rr < 8; rr++){
        int p = rr >> 1, r = rr & 1;
        int bg = b0 + 8*w + rr;
        float v0 = Lw[p*256 + 2*q        + r] + __ldg(gum + (size_t)bg*64 + q);
        float v1 = Lw[p*256 + 2*(q + 32) + r] + __ldg(gum + (size_t)bg*64 + 32 + q);
        float m = fmaxf(v0, v1);
        #pragma unroll
        for (int o = 16; o; o >>= 1) m = fmaxf(m, __shfl_xor_sync(0xffffffffu, m, o));
        float e0 = expf(v0 - m), e1 = expf(v1 - m);
        float s = e0 + e1;
        #pragma unroll
        for (int o = 16; o; o >>= 1) s += __shfl_xor_sync(0xffffffffu, s, o);
        float inv = 1.0f / s;
        out[(size_t)bg*64 + q]      = e0 * inv;
        out[(size_t)bg*64 + 32 + q] = e1 * inv;
    }
}

// ---------------------------------------------------------------------------
extern "C" void kernel_launch(void* const* d_in, const int* in_sizes, int n_in,
                              void* d_out, int out_size){
    const unsigned int* grid32 = (const unsigned int*)d_in[0];
    const float* gfeat  = (const float*)d_in[1];
    const float* gum    = (const float*)d_in[2];
    const float* enc_w1 = (const float*)d_in[3];
    const float* enc_b1 = (const float*)d_in[4];
    const float* enc_w2 = (const float*)d_in[5];
    const float* enc_b2 = (const float*)d_in[6];
    const float* wy     = (const float*)d_in[7];
    const float* by     = (const float*)d_in[8];
    const float* wz     = (const float*)d_in[9];
    const float* bz     = (const float*)d_in[10];
    const float* rz_w1  = (const float*)d_in[11];
    const float* rz_b1  = (const float*)d_in[12];
    const float* rz_w2  = (const float*)d_in[13];
    const float* rz_b2  = (const float*)d_in[14];
    const float* ry_w1  = (const float*)d_in[15];
    const float* ry_b1  = (const float*)d_in[16];
    const float* ry_w2  = (const float*)d_in[17];
    const float* ry_b2  = (const float*)d_in[18];
    const float* sel_w1 = (const float*)d_in[19];
    const float* sel_b1 = (const float*)d_in[20];
    const float* sel_w2 = (const float*)d_in[21];
    const float* sel_b2 = (const float*)d_in[22];
    float* out = (float*)d_out;

    cudaFuncSetAttribute(k_enc1, cudaFuncAttributeMaxDynamicSharedMemorySize, ENC1_SMEM);
    cudaFuncSetAttribute(k_rest, cudaFuncAttributeMaxDynamicSharedMemorySize, REST_SMEM_BYTES);

    k_detect<<<1, 32>>>(grid32);
    k_prep<<<2048, 256>>>(enc_w1, grid32, enc_w2, wy, wz, rz_w1, rz_w2, ry_w1, ry_w2, sel_w1, sel_w2);
    k_enc1<<<BB/64, 512, ENC1_SMEM>>>(enc_b1);
    k_rest<<<BB/32, 128, REST_SMEM_BYTES>>>(gfeat, gum,
        enc_b2, by, bz, rz_b1, rz_b2, ry_b1, ry_b2, sel_b1, sel_b2, out);
    (void)in_sizes; (void)n_in; (void)out_size;
}

// round 5
// speedup vs baseline: 1.2661x; 1.1492x over previous
#include <cuda_runtime.h>
#include <cuda_bf16.h>
#include <stdint.h>

#define BB   8192
#define GG   900
#define NC   10
#define HID  128
#define ADIM 128
#define ZDIM 64
#define GFD  16
#define RHID 64
#define NT   64

#define CHUNK 8
#define ROWB  (NC*HID*2)
#define STAGE_BYTES (CHUNK*ROWB)    /* 20480 */
#define COLORS_OFF  (2*STAGE_BYTES) /* 40960 */
#define ENC1_SMEM   (COLORS_OFF + 64*GG)   /* 98560 */

#define REST_SMEM_BYTES (12800*4)   /* 51200 */

/* bf16 weight blob offsets (elements) */
#define OFF_ENC2 0
#define OFF_WY   16384
#define OFF_WZ   32768
#define OFF_RZ1  40960
#define OFF_RZ2  54272
#define OFF_RY1  58368
#define OFF_RY2  71680
#define OFF_SEL1 79872
#define OFF_SEL2 88064
#define WR_TOTAL 92160

typedef unsigned long long u64;

static __device__ __nv_bfloat16 g_w1b[GG*NC*HID];
static __device__ __nv_bfloat16 g_wr[WR_TOTAL];
static __device__ unsigned char g_colors[BB*GG];
static __device__ float         g_h1[BB*HID];     // pair-interleaved
static __device__ int           g_is64;

__device__ __forceinline__ float gelu_f(float x){
    return 0.5f * x * (1.0f + erff(x * 0.7071067811865476f));
}

// ---- packed helpers -------------------------------------------------------
__device__ __forceinline__ u64 splat2(float v){
    u64 r; asm("mov.b64 %0, {%1, %1};" : "=l"(r) : "f"(v)); return r;
}
__device__ __forceinline__ u64 fma2(u64 a, u64 b, u64 c){
    u64 d; asm("fma.rn.f32x2 %0, %1, %2, %3;" : "=l"(d) : "l"(a), "l"(b), "l"(c)); return d;
}
__device__ __forceinline__ void unpack2(u64 v, float& lo, float& hi){
    asm("mov.b64 {%0, %1}, %2;" : "=f"(lo), "=f"(hi) : "l"(v));
}
__device__ __forceinline__ unsigned bfma2(unsigned a, unsigned b, unsigned c){
    unsigned d; asm("fma.rn.bf16x2 %0, %1, %2, %3;" : "=r"(d) : "r"(a), "r"(b), "r"(c)); return d;
}
__device__ __forceinline__ float blo(unsigned v){ return __uint_as_float(v << 16); }
__device__ __forceinline__ float bhi(unsigned v){ return __uint_as_float(v & 0xFFFF0000u); }

// ---------------------------------------------------------------------------
__global__ void k_detect(const unsigned int* __restrict__ g32){
    unsigned v = 0;
    if (threadIdx.x < 16) v = g32[2*threadIdx.x + 1];
    unsigned any = __ballot_sync(0xffffffffu, v != 0u);
    if (threadIdx.x == 0) g_is64 = (any == 0u) ? 1 : 0;
}

__device__ __forceinline__ void cvt_range(__nv_bfloat16* dst, const float* src, int n, int t, int stride){
    for (int i = t; i < n; i += stride) dst[i] = __float2bfloat16(src[i]);
}

__global__ void k_prep(const float* __restrict__ w1, const unsigned int* __restrict__ g32,
                       const float* __restrict__ enc_w2, const float* __restrict__ wy,
                       const float* __restrict__ wz,     const float* __restrict__ rz_w1,
                       const float* __restrict__ rz_w2,  const float* __restrict__ ry_w1,
                       const float* __restrict__ ry_w2,  const float* __restrict__ sel_w1,
                       const float* __restrict__ sel_w2){
    const int stride = gridDim.x * blockDim.x;
    const int t = blockIdx.x * blockDim.x + threadIdx.x;
    for (int i = t; i < GG*NC*HID; i += stride)
        g_w1b[i] = __float2bfloat16(w1[i]);
    cvt_range(g_wr + OFF_ENC2, enc_w2, 16384, t, stride);
    cvt_range(g_wr + OFF_WY,   wy,     16384, t, stride);
    cvt_range(g_wr + OFF_WZ,   wz,      8192, t, stride);
    cvt_range(g_wr + OFF_RZ1,  rz_w1,  13312, t, stride);
    cvt_range(g_wr + OFF_RZ2,  rz_w2,   4096, t, stride);
    cvt_range(g_wr + OFF_RY1,  ry_w1,  13312, t, stride);
    cvt_range(g_wr + OFF_RY2,  ry_w2,   8192, t, stride);
    cvt_range(g_wr + OFF_SEL1, sel_w1,  8192, t, stride);
    cvt_range(g_wr + OFF_SEL2, sel_w2,  4096, t, stride);
    const int is64 = g_is64;
    if (is64){
        for (int i = t; i < BB*GG; i += stride)
            g_colors[i] = (unsigned char)g32[2*i];
    } else {
        for (int i = t; i < BB*GG; i += stride)
            g_colors[i] = (unsigned char)g32[i];
    }
}

// ---------------------------------------------------------------------------
// Encoder layer 1: bf16x2 accumulation (fma with 1.0 multiplier).
// ---------------------------------------------------------------------------
__global__ __launch_bounds__(512) void k_enc1(const float* __restrict__ b1){
    extern __shared__ char smem[];
    unsigned char* colors = (unsigned char*)(smem + COLORS_OFF);
    const int tid = threadIdx.x;
    const int q = tid & 31, w = tid >> 5;
    const int bblock = blockIdx.x * 64;
    const unsigned ONES = 0x3F803F80u;

    for (int idx = tid; idx < 64*GG; idx += 512){
        int bl = idx / GG;
        int cell = idx - bl*GG;
        colors[cell*64 + bl] = g_colors[(bblock + bl)*GG + cell];
    }

    const unsigned smem_s = (unsigned)__cvta_generic_to_shared(smem);
    const char* wsrc = (const char*)g_w1b;

    auto issue = [&](int s){
        int base = s * CHUNK;
        if (base < GG){
            int cells = min(CHUNK, GG - base);
            int bytes = cells * ROWB;
            unsigned dbase = smem_s + (s & 1) * STAGE_BYTES;
            const char* sbase = wsrc + (size_t)base * ROWB;
            for (int off = tid*16; off < bytes; off += 512*16){
                asm volatile("cp.async.ca.shared.global [%0], [%1], 16;"
                             :: "r"(dbase + off), "l"(sbase + off));
            }
        }
        asm volatile("cp.async.commit_group;");
    };

    unsigned acc[4][2];
    #pragma unroll
    for (int ib = 0; ib < 4; ib++){ acc[ib][0] = 0u; acc[ib][1] = 0u; }

    issue(0); issue(1);
    const int NST = (GG + CHUNK - 1) / CHUNK;

    for (int s = 0; s < NST; s++){
        asm volatile("cp.async.wait_group 1;" ::: "memory");
        __syncthreads();
        const __nv_bfloat16* rbuf = (const __nv_bfloat16*)(smem + (s & 1) * STAGE_BYTES);
        const int cbase = s * CHUNK;
        const int cells = min(CHUNK, GG - cbase);

        auto body = [&](int ci){
            unsigned c4 = *(const unsigned*)(colors + (cbase + ci)*64 + w*4);
            #pragma unroll
            for (int ib = 0; ib < 4; ib++){
                int c = (c4 >> (8*ib)) & 0xFF;
                uint2 v = *(const uint2*)(rbuf + (ci*NC + c)*HID + q*4);
                acc[ib][0] = bfma2(v.x, ONES, acc[ib][0]);
                acc[ib][1] = bfma2(v.y, ONES, acc[ib][1]);
            }
        };
        if (cells == CHUNK){
            #pragma unroll
            for (int ci = 0; ci < CHUNK; ci++) body(ci);
        } else {
            for (int ci = 0; ci < cells; ci++) body(ci);
        }
        __syncthreads();
        issue(s + 2);
    }

    float bvv[4];
    { float4 bv = *(const float4*)(b1 + q*4); bvv[0]=bv.x; bvv[1]=bv.y; bvv[2]=bv.z; bvv[3]=bv.w; }
    #pragma unroll
    for (int ib = 0; ib < 4; ib += 2){
        int pair = (bblock + w*4 + ib) >> 1;
        #pragma unroll
        for (int j = 0; j < 4; j++){
            unsigned ua = acc[ib  ][j >> 1];
            unsigned ub = acc[ib+1][j >> 1];
            float va = (j & 1) ? bhi(ua) : blo(ua);
            float vb = (j & 1) ? bhi(ub) : blo(ub);
            float lo = gelu_f(va + bvv[j]);
            float hi = gelu_f(vb + bvv[j]);
            *(float2*)(g_h1 + (size_t)pair*256 + 2*(4*q + j)) = make_float2(lo, hi);
        }
    }
}

// ---------------------------------------------------------------------------
// k_rest v4: 2 pairs/warp, 8 warps/block (256 thr), grid 256 -> 2048 warps.
// ---------------------------------------------------------------------------
template<int C>
__device__ __forceinline__ void fma_row(u64 (&acc)[2][C], const unsigned (&wb)[C/2],
                                        const u64 a0, const u64 a1){
    #pragma unroll
    for (int c = 0; c < C; c++){
        unsigned v = wb[c >> 1];
        u64 ws = splat2((c & 1) ? bhi(v) : blo(v));
        acc[0][c] = fma2(a0, ws, acc[0][c]);
        acc[1][c] = fma2(a1, ws, acc[1][c]);
    }
}

template<int C, int LEN>
__device__ __forceinline__ void segb(u64 (&acc)[2][C], const unsigned* __restrict__ Wg,
                                     const int Ow, const float* sp, const int pstr, const int q){
    constexpr int CW = C/2;
    const unsigned* Wp = Wg + CW*q;
    unsigned w0[CW], w1[CW];
    u64 ax[2], ay[2];
    #pragma unroll
    for (int j = 0; j < CW; j++){ w0[j] = __ldg(Wp + j); w1[j] = __ldg(Wp + Ow + j); }
    #pragma unroll
    for (int p = 0; p < 2; p++){
        ulonglong2 t = *(const ulonglong2*)(sp + p*pstr);
        ax[p] = t.x; ay[p] = t.y;
    }
    #pragma unroll 2
    for (int i = 0; i < LEN - 2; i += 2){
        unsigned nw0[CW], nw1[CW];
        u64 nax[2], nay[2];
        #pragma unroll
        for (int j = 0; j < CW; j++){
            nw0[j] = __ldg(Wp + (i+2)*Ow + j);
            nw1[j] = __ldg(Wp + (i+3)*Ow + j);
        }
        #pragma unroll
        for (int p = 0; p < 2; p++){
            ulonglong2 t = *(const ulonglong2*)(sp + p*pstr + 2*(i+2));
            nax[p] = t.x; nay[p] = t.y;
        }
        fma_row<C>(acc, w0, ax[0], ax[1]);
        fma_row<C>(acc, w1, ay[0], ay[1]);
        #pragma unroll
        for (int j = 0; j < CW; j++){ w0[j] = nw0[j]; w1[j] = nw1[j]; }
        #pragma unroll
        for (int p = 0; p < 2; p++){ ax[p] = nax[p]; ay[p] = nay[p]; }
    }
    fma_row<C>(acc, w0, ax[0], ax[1]);
    fma_row<C>(acc, w1, ay[0], ay[1]);
}

template<int C>
__device__ __forceinline__ void wloadf(float (&wv)[C], const float* __restrict__ p){
    if (C == 4){ float4 v = *(const float4*)p; wv[0]=v.x; wv[1]=v.y; wv[2]=v.z; wv[3]=v.w; }
    else       { float2 v = *(const float2*)p; wv[0]=v.x; wv[1]=v.y; }
}

template<int C>
__device__ __forceinline__ void initb(u64 (&acc)[2][C], const float* __restrict__ B, const int q){
    float bv[C]; wloadf<C>(bv, B + C*q);
    #pragma unroll
    for (int c = 0; c < C; c++){
        u64 s = splat2(bv[c]);
        acc[0][c] = s; acc[1][c] = s;
    }
}

template<int C, bool ACT>
__device__ __forceinline__ void finish(u64 (&acc)[2][C], float* dp, const int pstr, const int q){
    #pragma unroll
    for (int p = 0; p < 2; p++)
        #pragma unroll
        for (int c = 0; c < C; c++){
            float lo, hi; unpack2(acc[p][c], lo, hi);
            if (ACT){ lo = gelu_f(lo); hi = gelu_f(hi); }
            *(float2*)(dp + p*pstr + 2*(C*q + c)) = make_float2(lo, hi);
        }
    __syncwarp();
}

__global__ __launch_bounds__(256) void k_rest(
    const float* __restrict__ gfeat, const float* __restrict__ gum,
    const float* __restrict__ enc_b2, const float* __restrict__ by,
    const float* __restrict__ bz,     const float* __restrict__ rz_b1,
    const float* __restrict__ rz_b2,  const float* __restrict__ ry_b1,
    const float* __restrict__ ry_b2,  const float* __restrict__ sel_b1,
    const float* __restrict__ sel_b2,
    float* __restrict__ out)
{
    extern __shared__ float sm[];
    float* Y  = sm;            // 4096 (16 pairs x 256)
    float* L  = sm + 4096;     // 4096
    float* Z  = sm + 8192;     // 2048
    float* T  = sm + 10240;    // 2048
    float* GF = sm + 12288;    // 512
    const int tid = threadIdx.x, q = tid & 31, w = tid >> 5;  // w: 0..7
    const int b0 = blockIdx.x * 32;
    const unsigned* WR = (const unsigned*)g_wr;

    for (int idx = tid; idx < 4096; idx += 256)
        Y[idx] = g_h1[(size_t)(b0 >> 1)*256 + idx];
    for (int idx = tid; idx < 32*16; idx += 256){
        int b = idx >> 4, i = idx & 15;
        GF[(b >> 1)*32 + 2*i + (b & 1)] = gfeat[(size_t)(b0 + b)*16 + i];
    }
    __syncthreads();

    float* Yw  = Y  + w*512;   // 2 pairs x 256
    float* Lw  = L  + w*512;
    float* Zw  = Z  + w*256;   // 2 pairs x 128
    float* Tw  = T  + w*256;
    float* GFw = GF + w*64;    // 2 pairs x 32

    // h2 = gelu(h1 @ enc_w2 + b2)
    { u64 acc[2][4]; initb<4>(acc, enc_b2, q); segb<4,128>(acc, WR + OFF_ENC2/2, 64, Yw, 256, q); finish<4,true >(acc, Lw, 256, q); }
    // y = h2 @ wy + by
    { u64 acc[2][4]; initb<4>(acc, by, q);     segb<4,128>(acc, WR + OFF_WY/2,   64, Lw, 256, q); finish<4,false>(acc, Yw, 256, q); }
    // z = h2 @ wz + bz
    { u64 acc[2][2]; initb<2>(acc, bz, q);     segb<2,128>(acc, WR + OFF_WZ/2,   32, Lw, 256, q); finish<2,false>(acc, Zw, 128, q); }

    #pragma unroll 1
    for (int cyc = 0; cyc < 3; cyc++){
        { u64 acc[2][2]; initb<2>(acc, rz_b1, q);
          segb<2,128>(acc, WR + OFF_RZ1/2,             32, Yw,  256, q);
          segb<2, 64>(acc, WR + (OFF_RZ1 + 128*64)/2,  32, Zw,  128, q);
          segb<2, 16>(acc, WR + (OFF_RZ1 + 192*64)/2,  32, GFw,  32, q);
          finish<2,true>(acc, Tw, 128, q); }
        { u64 acc[2][2]; initb<2>(acc, rz_b2, q); segb<2,64>(acc, WR + OFF_RZ2/2, 32, Tw, 128, q); finish<2,false>(acc, Zw, 128, q); }
        { u64 acc[2][2]; initb<2>(acc, ry_b1, q);
          segb<2, 64>(acc, WR + OFF_RY1/2,             32, Zw,  128, q);
          segb<2,128>(acc, WR + (OFF_RY1 +  64*64)/2,  32, Yw,  256, q);
          segb<2, 16>(acc, WR + (OFF_RY1 + 192*64)/2,  32, GFw,  32, q);
          finish<2,true>(acc, Tw, 128, q); }
        { u64 acc[2][4]; initb<4>(acc, ry_b2, q); segb<4,64>(acc, WR + OFF_RY2/2, 64, Tw, 128, q); finish<4,false>(acc, Yw, 256, q); }
    }

    { u64 acc[2][2]; initb<2>(acc, sel_b1, q); segb<2,128>(acc, WR + OFF_SEL1/2, 32, Yw, 256, q); finish<2,true >(acc, Tw, 128, q); }
    { u64 acc[2][2]; initb<2>(acc, sel_b2, q); segb<2, 64>(acc, WR + OFF_SEL2/2, 32, Tw, 128, q); finish<2,false>(acc, Lw, 256, q); }

    #pragma unroll 1
    for (int rr = 0; rr < 4; rr++){
        int p = rr >> 1, r = rr & 1;
        int bg = b0 + 4*w + rr;
        float v0 = Lw[p*256 + 2*q        + r] + __ldg(gum + (size_t)bg*64 + q);
        float v1 = Lw[p*256 + 2*(q + 32) + r] + __ldg(gum + (size_t)bg*64 + 32 + q);
        float m = fmaxf(v0, v1);
        #pragma unroll
        for (int o = 16; o; o >>= 1) m = fmaxf(m, __shfl_xor_sync(0xffffffffu, m, o));
        float e0 = expf(v0 - m), e1 = expf(v1 - m);
        float s = e0 + e1;
        #pragma unroll
        for (int o = 16; o; o >>= 1) s += __shfl_xor_sync(0xffffffffu, s, o);
        float inv = 1.0f / s;
        out[(size_t)bg*64 + q]      = e0 * inv;
        out[(size_t)bg*64 + 32 + q] = e1 * inv;
    }
}

// ---------------------------------------------------------------------------
extern "C" void kernel_launch(void* const* d_in, const int* in_sizes, int n_in,
                              void* d_out, int out_size){
    const unsigned int* grid32 = (const unsigned int*)d_in[0];
    const float* gfeat  = (const float*)d_in[1];
    const float* gum    = (const float*)d_in[2];
    const float* enc_w1 = (const float*)d_in[3];
    const float* enc_b1 = (const float*)d_in[4];
    const float* enc_w2 = (const float*)d_in[5];
    const float* enc_b2 = (const float*)d_in[6];
    const float* wy     = (const float*)d_in[7];
    const float* by     = (const float*)d_in[8];
    const float* wz     = (const float*)d_in[9];
    const float* bz     = (const float*)d_in[10];
    const float* rz_w1  = (const float*)d_in[11];
    const float* rz_b1  = (const float*)d_in[12];
    const float* rz_w2  = (const float*)d_in[13];
    const float* rz_b2  = (const float*)d_in[14];
    const float* ry_w1  = (const float*)d_in[15];
    const float* ry_b1  = (const float*)d_in[16];
    const float* ry_w2  = (const float*)d_in[17];
    const float* ry_b2  = (const float*)d_in[18];
    const float* sel_w1 = (const float*)d_in[19];
    const float* sel_b1 = (const float*)d_in[20];
    const float* sel_w2 = (const float*)d_in[21];
    const float* sel_b2 = (const float*)d_in[22];
    float* out = (float*)d_out;

    cudaFuncSetAttribute(k_enc1, cudaFuncAttributeMaxDynamicSharedMemorySize, ENC1_SMEM);
    cudaFuncSetAttribute(k_rest, cudaFuncAttributeMaxDynamicSharedMemorySize, REST_SMEM_BYTES);

    k_detect<<<1, 32>>>(grid32);
    k_prep<<<2048, 256>>>(enc_w1, grid32, enc_w2, wy, wz, rz_w1, rz_w2, ry_w1, ry_w2, sel_w1, sel_w2);
    k_enc1<<<BB/64, 512, ENC1_SMEM>>>(enc_b1);
    k_rest<<<BB/32, 256, REST_SMEM_BYTES>>>(gfeat, gum,
        enc_b2, by, bz, rz_b1, rz_b2, ry_b1, ry_b2, sel_b1, sel_b2, out);
    (void)in_sizes; (void)n_in; (void)out_size;
}

// round 8
// speedup vs baseline: 2.0890x; 1.6500x over previous
#include <cuda_runtime.h>
#include <cuda_bf16.h>
#include <stdint.h>

#define BB   8192
#define GG   900
#define NC   10
#define HID  128

/* ---- enc1 staging ---- */
#define CHUNK 8
#define ROWB  (NC*HID*2)
#define STAGE_BYTES (CHUNK*ROWB)
#define COLORS_OFF  (2*STAGE_BYTES)
#define ENC1_SMEM   (COLORS_OFF + 64*GG)

/* ---- transposed padded weight blob W^T[N][K+8] bf16 (byte offsets) ---- */
#define WT_ENC2 0        /* 128 x 136 = 34816 */
#define WT_WY   34816
#define WT_WZ   69632    /* 64 x 136 = 17408 */
#define WT_RZ1  87040    /* 64 x 216 = 27648 */
#define WT_RZ2  114688   /* 64 x 72  = 9216  */
#define WT_RY1  123904
#define WT_RY2  151552   /* 128 x 72 = 18432 */
#define WT_SEL1 169984
#define WT_SEL2 187392
#define WT_TOTAL 196608

/* ---- k_rest SMEM (bytes) ---- */
#define RS_BIAS 0        /* 768 floats */
#define RS_H1   3072     /* 64 x 272 */
#define RS_H2   20480    /* 64 x 272 */
#define RS_CAT  37888    /* 64 x 432 */
#define RS_T    65536    /* 64 x 144 */
#define RS_WD0  74752    /* 34816 */
#define RS_WD1  109568   /* 34816 */
#define RS_RZ1  144384
#define RS_RZ2  172032
#define RS_RY1  181248
#define RS_RY2  208896
#define RS_TOTAL 227328

/* bias float offsets */
#define BO_ENC2 0
#define BO_Y    128
#define BO_Z    256
#define BO_RZ1  320
#define BO_RZ2  384
#define BO_RY1  448
#define BO_RY2  512
#define BO_SEL1 640
#define BO_SEL2 704

static __device__ __nv_bfloat16 g_w1b[GG*NC*HID];
static __device__ __align__(16) __nv_bfloat16 g_wt[WT_TOTAL/2];
static __device__ __align__(16) __nv_bfloat16 g_h1b[(size_t)BB*HID];  /* row-major */
static __device__ unsigned char g_colors[BB*GG];
static __device__ int g_is64;

__device__ __forceinline__ float gelu_f(float x){
    return 0.5f * x * (1.0f + erff(x * 0.7071067811865476f));
}
__device__ __forceinline__ unsigned pack_bf2(float lo, float hi){
    unsigned d; asm("cvt.rn.bf16x2.f32 %0, %1, %2;" : "=r"(d) : "f"(hi), "f"(lo)); return d;
}
__device__ __forceinline__ unsigned bfma2(unsigned a, unsigned b, unsigned c){
    unsigned d; asm("fma.rn.bf16x2 %0, %1, %2, %3;" : "=r"(d) : "r"(a), "r"(b), "r"(c)); return d;
}
__device__ __forceinline__ float blo(unsigned v){ return __uint_as_float(v << 16); }
__device__ __forceinline__ float bhi(unsigned v){ return __uint_as_float(v & 0xFFFF0000u); }

#define CP_COMMIT() asm volatile("cp.async.commit_group;" ::: "memory")
#define CP_WAIT(N)  asm volatile("cp.async.wait_group %0;" :: "n"(N) : "memory")

__device__ __forceinline__ void cp16(uint32_t d, const void* s){
    asm volatile("cp.async.ca.shared.global [%0], [%1], 16;" :: "r"(d), "l"(s));
}
__device__ __forceinline__ void cpa(uint32_t dst, const void* src, int bytes, int tid){
    const char* s = (const char*)src;
    for (int off = tid*16; off < bytes; off += 128*16) cp16(dst + off, s + off);
}

/* ---- mma.sync / ldmatrix (baseline PTX, sm_80-compatible) ---- */
__device__ __forceinline__ uint4 ldm4(uint32_t a){
    uint4 r;
    asm volatile("ldmatrix.sync.aligned.m8n8.x4.shared.b16 {%0,%1,%2,%3}, [%4];"
        : "=r"(r.x), "=r"(r.y), "=r"(r.z), "=r"(r.w) : "r"(a));
    return r;
}
__device__ __forceinline__ void mma16816(float (&c)[4], const uint4& a, uint32_t b0, uint32_t b1){
    asm volatile("mma.sync.aligned.m16n8k16.row.col.f32.bf16.bf16.f32 "
        "{%0,%1,%2,%3},{%4,%5,%6,%7},{%8,%9},{%0,%1,%2,%3};"
        : "+f"(c[0]), "+f"(c[1]), "+f"(c[2]), "+f"(c[3])
        : "r"(a.x), "r"(a.y), "r"(a.z), "r"(a.w), "r"(b0), "r"(b1));
}

template<int KS, int NT>
__device__ __forceinline__ void gemm(float (&acc)[NT][4], uint32_t aLane, uint32_t wLane, int wStr){
    #pragma unroll
    for (int ks = 0; ks < KS; ks++){
        uint4 A = ldm4(aLane + ks*32);
        #pragma unroll
        for (int p = 0; p < NT/2; p++){
            uint4 B = ldm4(wLane + p*16*wStr + ks*32);
            mma16816(acc[2*p],   A, B.x, B.y);
            mma16816(acc[2*p+1], A, B.z, B.w);
        }
    }
}
template<int NT>
__device__ __forceinline__ void initacc(float (&acc)[NT][4], const float* bias, int t){
    #pragma unroll
    for (int nt = 0; nt < NT; nt++){
        float b0 = bias[nt*8 + 2*t], b1 = bias[nt*8 + 2*t + 1];
        acc[nt][0] = b0; acc[nt][1] = b1; acc[nt][2] = b0; acc[nt][3] = b1;
    }
}
template<int NT, bool ACT>
__device__ __forceinline__ void storeacc(float (&acc)[NT][4], uint32_t oL0, uint32_t oL1){
    #pragma unroll
    for (int nt = 0; nt < NT; nt++){
        float v0 = acc[nt][0], v1 = acc[nt][1], v2 = acc[nt][2], v3 = acc[nt][3];
        if (ACT){ v0 = gelu_f(v0); v1 = gelu_f(v1); v2 = gelu_f(v2); v3 = gelu_f(v3); }
        unsigned u0 = pack_bf2(v0, v1), u1 = pack_bf2(v2, v3);
        asm volatile("st.shared.b32 [%0], %1;" :: "r"(oL0 + nt*16), "r"(u0));
        asm volatile("st.shared.b32 [%0], %1;" :: "r"(oL1 + nt*16), "r"(u1));
    }
    __syncwarp();
}
template<int KS, int NT, bool ACT>
__device__ __forceinline__ void layer(uint32_t aLane, uint32_t wLane, int wStr,
                                      const float* bias, int t, uint32_t oL0, uint32_t oL1){
    float acc[NT][4];
    initacc<NT>(acc, bias, t);
    gemm<KS, NT>(acc, aLane, wLane, wStr);
    storeacc<NT, ACT>(acc, oL0, oL1);
}

/* ---------------------------------------------------------------------- */
__global__ void k_detect(const unsigned int* __restrict__ g32){
    unsigned v = 0;
    if (threadIdx.x < 16) v = g32[2*threadIdx.x + 1];
    unsigned any = __ballot_sync(0xffffffffu, v != 0u);
    if (threadIdx.x == 0) g_is64 = (any == 0u) ? 1 : 0;
}

/* dst[n][k] (stride Kp) = W[src(k)][n], W row-major [K][N] */
__device__ void build_wt(__nv_bfloat16* dst, const float* __restrict__ W, int N, int K, int Kp,
                         int mode, int t, int stride){
    int total = N * K;
    for (int idx = t; idx < total; idx += stride){
        int n = idx / K, k = idx - n*K;
        int src = k;
        if (mode == 1) src = (k < 128) ? (64 + k) : ((k < 192) ? (k - 128) : k);
        dst[(size_t)n*Kp + k] = __float2bfloat16(W[(size_t)src*N + n]);
    }
}

__global__ void k_prep(const float* __restrict__ w1, const unsigned int* __restrict__ g32,
                       const float* __restrict__ enc_w2, const float* __restrict__ wy,
                       const float* __restrict__ wz,     const float* __restrict__ rz_w1,
                       const float* __restrict__ rz_w2,  const float* __restrict__ ry_w1,
                       const float* __restrict__ ry_w2,  const float* __restrict__ sel_w1,
                       const float* __restrict__ sel_w2){
    const int stride = gridDim.x * blockDim.x;
    const int t = blockIdx.x * blockDim.x + threadIdx.x;
    for (int i = t; i < GG*NC*HID; i += stride)
        g_w1b[i] = __float2bfloat16(w1[i]);
    build_wt(g_wt + WT_ENC2/2, enc_w2, 128, 128, 136, 0, t, stride);
    build_wt(g_wt + WT_WY/2,   wy,     128, 128, 136, 0, t, stride);
    build_wt(g_wt + WT_WZ/2,   wz,      64, 128, 136, 0, t, stride);
    build_wt(g_wt + WT_RZ1/2,  rz_w1,   64, 208, 216, 0, t, stride);
    build_wt(g_wt + WT_RZ2/2,  rz_w2,   64,  64,  72, 0, t, stride);
    build_wt(g_wt + WT_RY1/2,  ry_w1,   64, 208, 216, 1, t, stride);
    build_wt(g_wt + WT_RY2/2,  ry_w2,  128,  64,  72, 0, t, stride);
    build_wt(g_wt + WT_SEL1/2, sel_w1,  64, 128, 136, 0, t, stride);
    build_wt(g_wt + WT_SEL2/2, sel_w2,  64,  64,  72, 0, t, stride);
    const int is64 = g_is64;
    if (is64){
        for (int i = t; i < BB*GG; i += stride)
            g_colors[i] = (unsigned char)g32[2*i];
    } else {
        for (int i = t; i < BB*GG; i += stride)
            g_colors[i] = (unsigned char)g32[i];
    }
}

/* ---------------------------------------------------------------------- */
/* Encoder layer 1: bf16x2 gather-accumulate; h1 row-major bf16.          */
/* ---------------------------------------------------------------------- */
__global__ __launch_bounds__(512) void k_enc1(const float* __restrict__ b1){
    extern __shared__ char smem[];
    unsigned char* colors = (unsigned char*)(smem + COLORS_OFF);
    const int tid = threadIdx.x;
    const int q = tid & 31, w = tid >> 5;
    const int bblock = blockIdx.x * 64;
    const unsigned ONES = 0x3F803F80u;

    for (int idx = tid; idx < 64*GG; idx += 512){
        int bl = idx / GG;
        int cell = idx - bl*GG;
        colors[cell*64 + bl] = g_colors[(bblock + bl)*GG + cell];
    }

    const unsigned smem_s = (unsigned)__cvta_generic_to_shared(smem);
    const char* wsrc = (const char*)g_w1b;

    auto issue = [&](int s){
        int base = s * CHUNK;
        if (base < GG){
            int cells = min(CHUNK, GG - base);
            int bytes = cells * ROWB;
            unsigned dbase = smem_s + (s & 1) * STAGE_BYTES;
            const char* sbase = wsrc + (size_t)base * ROWB;
            for (int off = tid*16; off < bytes; off += 512*16) cp16(dbase + off, sbase + off);
        }
        CP_COMMIT();
    };

    unsigned acc[4][2];
    #pragma unroll
    for (int ib = 0; ib < 4; ib++){ acc[ib][0] = 0u; acc[ib][1] = 0u; }

    issue(0); issue(1);
    const int NST = (GG + CHUNK - 1) / CHUNK;

    for (int s = 0; s < NST; s++){
        asm volatile("cp.async.wait_group 1;" ::: "memory");
        __syncthreads();
        const __nv_bfloat16* rbuf = (const __nv_bfloat16*)(smem + (s & 1) * STAGE_BYTES);
        const int cbase = s * CHUNK;
        const int cells = min(CHUNK, GG - cbase);

        auto body = [&](int ci){
            unsigned c4 = *(const unsigned*)(colors + (cbase + ci)*64 + w*4);
            #pragma unroll
            for (int ib = 0; ib < 4; ib++){
                int c = (c4 >> (8*ib)) & 0xFF;
                uint2 v = *(const uint2*)(rbuf + (ci*NC + c)*HID + q*4);
                acc[ib][0] = bfma2(v.x, ONES, acc[ib][0]);
                acc[ib][1] = bfma2(v.y, ONES, acc[ib][1]);
            }
        };
        if (cells == CHUNK){
            #pragma unroll
            for (int ci = 0; ci < CHUNK; ci++) body(ci);
        } else {
            for (int ci = 0; ci < cells; ci++) body(ci);
        }
        __syncthreads();
        issue(s + 2);
    }

    float bvv[4];
    { float4 bv = *(const float4*)(b1 + q*4); bvv[0]=bv.x; bvv[1]=bv.y; bvv[2]=bv.z; bvv[3]=bv.w; }
    #pragma unroll
    for (int ib = 0; ib < 4; ib++){
        int bg = bblock + w*4 + ib;
        float v0 = gelu_f(blo(acc[ib][0]) + bvv[0]);
        float v1 = gelu_f(bhi(acc[ib][0]) + bvv[1]);
        float v2 = gelu_f(blo(acc[ib][1]) + bvv[2]);
        float v3 = gelu_f(bhi(acc[ib][1]) + bvv[3]);
        *(uint2*)(g_h1b + (size_t)bg*HID + 4*q) = make_uint2(pack_bf2(v0, v1), pack_bf2(v2, v3));
    }
}

/* ---------------------------------------------------------------------- */
/* k_rest via mma.sync: 64 rows/CTA, 4 warps x 16 rows, warp-private.     */
/* ---------------------------------------------------------------------- */
__global__ __launch_bounds__(128) void k_rest(
    const float* __restrict__ gfeat, const float* __restrict__ gum,
    const float* __restrict__ enc_b2, const float* __restrict__ by,
    const float* __restrict__ bz,     const float* __restrict__ rz_b1,
    const float* __restrict__ rz_b2,  const float* __restrict__ ry_b1,
    const float* __restrict__ ry_b2,  const float* __restrict__ sel_b1,
    const float* __restrict__ sel_b2,
    float* __restrict__ out)
{
    extern __shared__ char smem[];
    const int tid = threadIdx.x, lane = tid & 31, warp = tid >> 5;
    const int t = lane & 3, g = lane >> 2;
    const int b0 = blockIdx.x * 64;
    const uint32_t su = (uint32_t)__cvta_generic_to_shared(smem);
    float* bs = (float*)smem;

    /* bias staging (plain loads, published by first syncthreads) */
    bs[BO_ENC2 + tid] = enc_b2[tid];
    bs[BO_Y + tid]    = by[tid];
    bs[BO_RY2 + tid]  = ry_b2[tid];
    if (tid < 64){
        bs[BO_Z + tid]    = bz[tid];
        bs[BO_RZ1 + tid]  = rz_b1[tid];
        bs[BO_RZ2 + tid]  = rz_b2[tid];
        bs[BO_RY1 + tid]  = ry_b1[tid];
        bs[BO_SEL1 + tid] = sel_b1[tid];
        bs[BO_SEL2 + tid] = sel_b2[tid];
    }

    /* C0: H1 (64 x 256B -> stride 272) + enc2 */
    for (int i = tid; i < 64*16; i += 128){
        int r = i >> 4, ch = i & 15;
        cp16(su + RS_H1 + r*272 + ch*16, (const char*)g_h1b + (size_t)(b0 + r)*256 + ch*16);
    }
    cpa(su + RS_WD0, (const char*)g_wt + WT_ENC2, 34816, tid);
    CP_COMMIT();
    /* C1: wy */
    cpa(su + RS_WD1, (const char*)g_wt + WT_WY, 34816, tid);
    CP_COMMIT();
    /* C2: persistent refine weights */
    cpa(su + RS_RZ1, (const char*)g_wt + WT_RZ1, 27648, tid);
    cpa(su + RS_RZ2, (const char*)g_wt + WT_RZ2,  9216, tid);
    cpa(su + RS_RY1, (const char*)g_wt + WT_RY1, 27648, tid);
    cpa(su + RS_RY2, (const char*)g_wt + WT_RY2, 18432, tid);
    CP_COMMIT();

    /* gf -> CAT cols 192:207 (byte 384) */
    if (tid < 64){
        const float4* gp = (const float4*)(gfeat + (size_t)(b0 + tid)*16);
        float4 f0 = __ldg(gp), f1 = __ldg(gp+1), f2 = __ldg(gp+2), f3 = __ldg(gp+3);
        char* row = smem + RS_CAT + tid*432 + 384;
        *(uint4*)(row)      = make_uint4(pack_bf2(f0.x,f0.y), pack_bf2(f0.z,f0.w),
                                         pack_bf2(f1.x,f1.y), pack_bf2(f1.z,f1.w));
        *(uint4*)(row + 16) = make_uint4(pack_bf2(f2.x,f2.y), pack_bf2(f2.z,f2.w),
                                         pack_bf2(f3.x,f3.y), pack_bf2(f3.z,f3.w));
    }
    CP_WAIT(2);           /* C0 done */
    __syncthreads();

    /* per-lane fragment addressing */
    const uint32_t arow = (uint32_t)(lane & 15), ahalf = (uint32_t)((lane >> 4) * 16);
    const uint32_t brow = (uint32_t)(((lane >> 4) & 1)*8 + (lane & 7));
    const uint32_t bhalf = (uint32_t)(((lane >> 3) & 1) * 16);
    #define ALANE(base, str) ((base) + arow*(str) + ahalf)
    #define WLANE(base, str) ((base) + brow*(str) + bhalf)
    #define OL(base, str)    ((base) + (uint32_t)g*(str) + (uint32_t)t*4), \
                             ((base) + (uint32_t)(g+8)*(str) + (uint32_t)t*4)

    const uint32_t H1w  = su + RS_H1  + warp*16*272;
    const uint32_t H2w  = su + RS_H2  + warp*16*272;
    const uint32_t CATw = su + RS_CAT + warp*16*432;
    const uint32_t Tw   = su + RS_T   + warp*16*144;

    /* L1: h2 = gelu(h1 @ enc_w2 + b) */
    layer<8,16,true>(ALANE(H1w,272), WLANE(su+RS_WD0,272), 272, bs+BO_ENC2, t, OL(H2w,272));
    __syncthreads();
    /* C3: wz -> H1 region (dead); C4: sel1 -> WD0 */
    cpa(su + RS_H1,  (const char*)g_wt + WT_WZ,   17408, tid); CP_COMMIT();
    cpa(su + RS_WD0, (const char*)g_wt + WT_SEL1, 17408, tid); CP_COMMIT();
    CP_WAIT(3);           /* C1 (wy) done */
    __syncthreads();

    /* L2: y -> CAT cols 0:127 */
    layer<8,16,false>(ALANE(H2w,272), WLANE(su+RS_WD1,272), 272, bs+BO_Y, t, OL(CATw,432));
    CP_WAIT(1);           /* C2 (persist) + C3 (wz) done */
    __syncthreads();
    /* L3: z -> CAT cols 128:191 (byte 256) */
    layer<8,8,false>(ALANE(H2w,272), WLANE(su+RS_H1,272), 272, bs+BO_Z, t, OL(CATw+256,432));
    __syncthreads();
    /* C5: sel2 -> WD1 (wy dead) */
    cpa(su + RS_WD1, (const char*)g_wt + WT_SEL2, 9216, tid); CP_COMMIT();

    /* refinement cycles (warp-private; no block syncs) */
    #pragma unroll 1
    for (int cyc = 0; cyc < 3; cyc++){
        layer<13,8,true >(ALANE(CATw,432), WLANE(su+RS_RZ1,216*2), 216*2, bs+BO_RZ1, t, OL(Tw,144));
        layer<4, 8,false>(ALANE(Tw,144),   WLANE(su+RS_RZ2, 72*2),  72*2, bs+BO_RZ2, t, OL(CATw+256,432));
        layer<13,8,true >(ALANE(CATw,432), WLANE(su+RS_RY1,216*2), 216*2, bs+BO_RY1, t, OL(Tw,144));
        layer<4,16,false>(ALANE(Tw,144),   WLANE(su+RS_RY2, 72*2),  72*2, bs+BO_RY2, t, OL(CATw,432));
    }

    CP_WAIT(1);           /* C4 (sel1) done */
    __syncthreads();
    /* sel1: A = CAT cols 0:127 */
    layer<8,8,true>(ALANE(CATw,432), WLANE(su+RS_WD0,272), 272, bs+BO_SEL1, t, OL(Tw,144));
    CP_WAIT(0);
    __syncthreads();

    /* logits + softmax */
    {
        float acc[8][4];
        initacc<8>(acc, bs + BO_SEL2, t);
        gemm<4,8>(acc, ALANE(Tw,144), WLANE(su+RS_WD1,144), 144);

        int rA = b0 + warp*16 + g, rB = rA + 8;
        float eA[16], eB[16];
        float mA = -1e30f, mB = -1e30f;
        #pragma unroll
        for (int nt = 0; nt < 8; nt++){
            float2 ga = *(const float2*)(gum + (size_t)rA*64 + nt*8 + 2*t);
            float2 gb = *(const float2*)(gum + (size_t)rB*64 + nt*8 + 2*t);
            eA[2*nt]   = acc[nt][0] + ga.x;  eA[2*nt+1] = acc[nt][1] + ga.y;
            eB[2*nt]   = acc[nt][2] + gb.x;  eB[2*nt+1] = acc[nt][3] + gb.y;
            mA = fmaxf(mA, fmaxf(eA[2*nt], eA[2*nt+1]));
            mB = fmaxf(mB, fmaxf(eB[2*nt], eB[2*nt+1]));
        }
        mA = fmaxf(mA, __shfl_xor_sync(0xffffffffu, mA, 1));
        mA = fmaxf(mA, __shfl_xor_sync(0xffffffffu, mA, 2));
        mB = fmaxf(mB, __shfl_xor_sync(0xffffffffu, mB, 1));
        mB = fmaxf(mB, __shfl_xor_sync(0xffffffffu, mB, 2));
        float sA = 0.0f, sB = 0.0f;
        #pragma unroll
        for (int i = 0; i < 16; i++){
            eA[i] = expf(eA[i] - mA); sA += eA[i];
            eB[i] = expf(eB[i] - mB); sB += eB[i];
        }
        sA += __shfl_xor_sync(0xffffffffu, sA, 1);
        sA += __shfl_xor_sync(0xffffffffu, sA, 2);
        sB += __shfl_xor_sync(0xffffffffu, sB, 1);
        sB += __shfl_xor_sync(0xffffffffu, sB, 2);
        float iA = 1.0f / sA, iB = 1.0f / sB;
        #pragma unroll
        for (int nt = 0; nt < 8; nt++){
            *(float2*)(out + (size_t)rA*64 + nt*8 + 2*t) = make_float2(eA[2*nt]*iA, eA[2*nt+1]*iA);
            *(float2*)(out + (size_t)rB*64 + nt*8 + 2*t) = make_float2(eB[2*nt]*iB, eB[2*nt+1]*iB);
        }
    }
    #undef ALANE
    #undef WLANE
    #undef OL
}

/* ---------------------------------------------------------------------- */
extern "C" void kernel_launch(void* const* d_in, const int* in_sizes, int n_in,
                              void* d_out, int out_size){
    const unsigned int* grid32 = (const unsigned int*)d_in[0];
    const float* gfeat  = (const float*)d_in[1];
    const float* gum    = (const float*)d_in[2];
    const float* enc_w1 = (const float*)d_in[3];
    const float* enc_b1 = (const float*)d_in[4];
    const float* enc_w2 = (const float*)d_in[5];
    const float* enc_b2 = (const float*)d_in[6];
    const float* wy     = (const float*)d_in[7];
    const float* by     = (const float*)d_in[8];
    const float* wz     = (const float*)d_in[9];
    const float* bz     = (const float*)d_in[10];
    const float* rz_w1  = (const float*)d_in[11];
    const float* rz_b1  = (const float*)d_in[12];
    const float* rz_w2  = (const float*)d_in[13];
    const float* rz_b2  = (const float*)d_in[14];
    const float* ry_w1  = (const float*)d_in[15];
    const float* ry_b1  = (const float*)d_in[16];
    const float* ry_w2  = (const float*)d_in[17];
    const float* ry_b2  = (const float*)d_in[18];
    const float* sel_w1 = (const float*)d_in[19];
    const float* sel_b1 = (const float*)d_in[20];
    const float* sel_w2 = (const float*)d_in[21];
    const float* sel_b2 = (const float*)d_in[22];
    float* out = (float*)d_out;

    cudaFuncSetAttribute(k_enc1, cudaFuncAttributeMaxDynamicSharedMemorySize, ENC1_SMEM);
    cudaFuncSetAttribute(k_rest, cudaFuncAttributeMaxDynamicSharedMemorySize, RS_TOTAL);

    k_detect<<<1, 32>>>(grid32);
    k_prep<<<2048, 256>>>(enc_w1, grid32, enc_w2, wy, wz, rz_w1, rz_w2, ry_w1, ry_w2, sel_w1, sel_w2);
    k_enc1<<<BB/64, 512, ENC1_SMEM>>>(enc_b1);
    k_rest<<<BB/64, 128, RS_TOTAL>>>(gfeat, gum,
        enc_b2, by, bz, rz_b1, rz_b2, ry_b1, ry_b2, sel_b1, sel_b2, out);
    (void)in_sizes; (void)n_in; (void)out_size;
}

// round 9
// speedup vs baseline: 2.1900x; 1.0483x over previous
#include <cuda_runtime.h>
#include <cuda_bf16.h>
#include <stdint.h>

#define BB   8192
#define GG   900
#define NC   10
#define HID  128

/* ---- enc1 staging ---- */
#define CHUNK 8
#define ROWB  (NC*HID*2)
#define STAGE_BYTES (CHUNK*ROWB)
#define COLORS_OFF  (2*STAGE_BYTES)
#define ENC1_SMEM   (COLORS_OFF + 64*GG)

/* ---- transposed padded weight blob W^T[N][K+8] bf16 (byte offsets) ---- */
#define WT_ENC2 0        /* 128 x 136 = 34816 */
#define WT_WY   34816
#define WT_WZ   69632    /* 64 x 136 = 17408 */
#define WT_RZ1  87040    /* 64 x 216 = 27648 */
#define WT_RZ2  114688   /* 64 x 72  = 9216  */
#define WT_RY1  123904
#define WT_RY2  151552   /* 128 x 72 = 18432 */
#define WT_SEL1 169984
#define WT_SEL2 187392
#define WT_TOTAL 196608

/* ---- k_rest SMEM (bytes) ---- */
#define RS_BIAS 0        /* 768 floats */
#define RS_H1   3072     /* 64 x 272 */
#define RS_H2   20480    /* 64 x 272 */
#define RS_CAT  37888    /* 64 x 432 ; reused as f32 logits 64x64 */
#define RS_T    65536    /* 64 x 144 */
#define RS_WD0  74752    /* 34816 */
#define RS_WD1  109568   /* 34816 */
#define RS_RZ1  144384
#define RS_RZ2  172032
#define RS_RY1  181248
#define RS_RY2  208896
#define RS_TOTAL 227328

/* bias float offsets */
#define BO_ENC2 0
#define BO_Y    128
#define BO_Z    256
#define BO_RZ1  320
#define BO_RZ2  384
#define BO_RY1  448
#define BO_RY2  512
#define BO_SEL1 640
#define BO_SEL2 704

static __device__ __nv_bfloat16 g_w1b[GG*NC*HID];
static __device__ __align__(16) __nv_bfloat16 g_wt[WT_TOTAL/2];
static __device__ __align__(16) __nv_bfloat16 g_h1b[(size_t)BB*HID];  /* row-major */
static __device__ __align__(16) unsigned char g_colors[BB*GG];
static __device__ int g_is64;

__device__ __forceinline__ float gelu_f(float x){
    return 0.5f * x * (1.0f + erff(x * 0.7071067811865476f));
}
__device__ __forceinline__ unsigned pack_bf2(float lo, float hi){
    unsigned d; asm("cvt.rn.bf16x2.f32 %0, %1, %2;" : "=r"(d) : "f"(hi), "f"(lo)); return d;
}
__device__ __forceinline__ unsigned bfma2(unsigned a, unsigned b, unsigned c){
    unsigned d; asm("fma.rn.bf16x2 %0, %1, %2, %3;" : "=r"(d) : "r"(a), "r"(b), "r"(c)); return d;
}
__device__ __forceinline__ float blo(unsigned v){ return __uint_as_float(v << 16); }
__device__ __forceinline__ float bhi(unsigned v){ return __uint_as_float(v & 0xFFFF0000u); }

#define CP_COMMIT() asm volatile("cp.async.commit_group;" ::: "memory")
#define CP_WAIT(N)  asm volatile("cp.async.wait_group %0;" :: "n"(N) : "memory")

__device__ __forceinline__ void cp16(uint32_t d, const void* s){
    asm volatile("cp.async.ca.shared.global [%0], [%1], 16;" :: "r"(d), "l"(s));
}
__device__ __forceinline__ void cpa(uint32_t dst, const void* src, int bytes, int tid, int nthr){
    const char* s = (const char*)src;
    for (int off = tid*16; off < bytes; off += nthr*16) cp16(dst + off, s + off);
}

/* ---- mma.sync / ldmatrix (baseline PTX) ---- */
__device__ __forceinline__ uint4 ldm4(uint32_t a){
    uint4 r;
    asm volatile("ldmatrix.sync.aligned.m8n8.x4.shared.b16 {%0,%1,%2,%3}, [%4];"
        : "=r"(r.x), "=r"(r.y), "=r"(r.z), "=r"(r.w) : "r"(a));
    return r;
}
__device__ __forceinline__ void mma16816(float (&c)[4], const uint4& a, uint32_t b0, uint32_t b1){
    asm volatile("mma.sync.aligned.m16n8k16.row.col.f32.bf16.bf16.f32 "
        "{%0,%1,%2,%3},{%4,%5,%6,%7},{%8,%9},{%0,%1,%2,%3};"
        : "+f"(c[0]), "+f"(c[1]), "+f"(c[2]), "+f"(c[3])
        : "r"(a.x), "r"(a.y), "r"(a.z), "r"(a.w), "r"(b0), "r"(b1));
}

template<int KS, int NT>
__device__ __forceinline__ void gemm(float (&acc)[NT][4], uint32_t aLane, uint32_t wLane, int wStr){
    #pragma unroll
    for (int ks = 0; ks < KS; ks++){
        uint4 A = ldm4(aLane + ks*32);
        #pragma unroll
        for (int p = 0; p < NT/2; p++){
            uint4 B = ldm4(wLane + p*16*wStr + ks*32);
            mma16816(acc[2*p],   A, B.x, B.y);
            mma16816(acc[2*p+1], A, B.z, B.w);
        }
    }
}
template<int NT>
__device__ __forceinline__ void initacc(float (&acc)[NT][4], const float* bias, int t){
    #pragma unroll
    for (int nt = 0; nt < NT; nt++){
        float b0 = bias[nt*8 + 2*t], b1 = bias[nt*8 + 2*t + 1];
        acc[nt][0] = b0; acc[nt][1] = b1; acc[nt][2] = b0; acc[nt][3] = b1;
    }
}
template<int NT, bool ACT>
__device__ __forceinline__ void storeacc(float (&acc)[NT][4], uint32_t oL0, uint32_t oL1){
    #pragma unroll
    for (int nt = 0; nt < NT; nt++){
        float v0 = acc[nt][0], v1 = acc[nt][1], v2 = acc[nt][2], v3 = acc[nt][3];
        if (ACT){ v0 = gelu_f(v0); v1 = gelu_f(v1); v2 = gelu_f(v2); v3 = gelu_f(v3); }
        unsigned u0 = pack_bf2(v0, v1), u1 = pack_bf2(v2, v3);
        asm volatile("st.shared.b32 [%0], %1;" :: "r"(oL0 + nt*16), "r"(u0));
        asm volatile("st.shared.b32 [%0], %1;" :: "r"(oL1 + nt*16), "r"(u1));
    }
}
template<int KS, int NT, bool ACT>
__device__ __forceinline__ void layer(uint32_t aLane, uint32_t wLane, int wStr,
                                      const float* bias, int t, uint32_t oL0, uint32_t oL1){
    float acc[NT][4];
    initacc<NT>(acc, bias, t);
    gemm<KS, NT>(acc, aLane, wLane, wStr);
    storeacc<NT, ACT>(acc, oL0, oL1);
}

/* ---------------------------------------------------------------------- */
__global__ void k_detect(const unsigned int* __restrict__ g32){
    unsigned v = 0;
    if (threadIdx.x < 16) v = g32[2*threadIdx.x + 1];
    unsigned any = __ballot_sync(0xffffffffu, v != 0u);
    if (threadIdx.x == 0) g_is64 = (any == 0u) ? 1 : 0;
}

/* dst[n][k] (stride Kp) = W[src(k)][n], W row-major [K][N] */
__device__ void build_wt(__nv_bfloat16* dst, const float* __restrict__ W, int N, int K, int Kp,
                         int mode, int t, int stride){
    int total = N * K;
    for (int idx = t; idx < total; idx += stride){
        int n = idx / K, k = idx - n*K;
        int src = k;
        if (mode == 1) src = (k < 128) ? (64 + k) : ((k < 192) ? (k - 128) : k);
        dst[(size_t)n*Kp + k] = __float2bfloat16(W[(size_t)src*N + n]);
    }
}

__global__ void k_prep(const float* __restrict__ w1, const unsigned int* __restrict__ g32,
                       const float* __restrict__ enc_w2, const float* __restrict__ wy,
                       const float* __restrict__ wz,     const float* __restrict__ rz_w1,
                       const float* __restrict__ rz_w2,  const float* __restrict__ ry_w1,
                       const float* __restrict__ ry_w2,  const float* __restrict__ sel_w1,
                       const float* __restrict__ sel_w2){
    const int stride = gridDim.x * blockDim.x;
    const int t = blockIdx.x * blockDim.x + threadIdx.x;
    /* w1 -> bf16, vectorized 4 at a time */
    {
        const float4* s = (const float4*)w1;
        uint2* d = (uint2*)g_w1b;
        for (int i = t; i < GG*NC*HID/4; i += stride){
            float4 v = s[i];
            d[i] = make_uint2(pack_bf2(v.x, v.y), pack_bf2(v.z, v.w));
        }
    }
    build_wt(g_wt + WT_ENC2/2, enc_w2, 128, 128, 136, 0, t, stride);
    build_wt(g_wt + WT_WY/2,   wy,     128, 128, 136, 0, t, stride);
    build_wt(g_wt + WT_WZ/2,   wz,      64, 128, 136, 0, t, stride);
    build_wt(g_wt + WT_RZ1/2,  rz_w1,   64, 208, 216, 0, t, stride);
    build_wt(g_wt + WT_RZ2/2,  rz_w2,   64,  64,  72, 0, t, stride);
    build_wt(g_wt + WT_RY1/2,  ry_w1,   64, 208, 216, 1, t, stride);
    build_wt(g_wt + WT_RY2/2,  ry_w2,  128,  64,  72, 0, t, stride);
    build_wt(g_wt + WT_SEL1/2, sel_w1,  64, 128, 136, 0, t, stride);
    build_wt(g_wt + WT_SEL2/2, sel_w2,  64,  64,  72, 0, t, stride);
    /* colors, 4 per store */
    const int is64 = g_is64;
    uchar4* cd = (uchar4*)g_colors;
    if (is64){
        const ulonglong2* gp = (const ulonglong2*)g32;
        for (int i = t; i < BB*GG/4; i += stride){
            ulonglong2 a = gp[2*i], b = gp[2*i+1];
            cd[i] = make_uchar4((unsigned char)a.x, (unsigned char)a.y,
                                (unsigned char)b.x, (unsigned char)b.y);
        }
    } else {
        const uint4* gp = (const uint4*)g32;
        for (int i = t; i < BB*GG/4; i += stride){
            uint4 v = gp[i];
            cd[i] = make_uchar4((unsigned char)v.x, (unsigned char)v.y,
                                (unsigned char)v.z, (unsigned char)v.w);
        }
    }
}

/* ---------------------------------------------------------------------- */
/* Encoder layer 1: bf16x2 gather-accumulate; h1 row-major bf16.          */
/* ---------------------------------------------------------------------- */
__global__ __launch_bounds__(512) void k_enc1(const float* __restrict__ b1){
    extern __shared__ char smem[];
    unsigned char* colors = (unsigned char*)(smem + COLORS_OFF);
    const int tid = threadIdx.x;
    const int q = tid & 31, w = tid >> 5;
    const int bblock = blockIdx.x * 64;
    const unsigned ONES = 0x3F803F80u;

    for (int idx = tid; idx < 64*GG; idx += 512){
        int bl = idx / GG;
        int cell = idx - bl*GG;
        colors[cell*64 + bl] = g_colors[(bblock + bl)*GG + cell];
    }

    const unsigned smem_s = (unsigned)__cvta_generic_to_shared(smem);
    const char* wsrc = (const char*)g_w1b;

    auto issue = [&](int s){
        int base = s * CHUNK;
        if (base < GG){
            int cells = min(CHUNK, GG - base);
            int bytes = cells * ROWB;
            unsigned dbase = smem_s + (s & 1) * STAGE_BYTES;
            const char* sbase = wsrc + (size_t)base * ROWB;
            for (int off = tid*16; off < bytes; off += 512*16) cp16(dbase + off, sbase + off);
        }
        CP_COMMIT();
    };

    unsigned acc[4][2];
    #pragma unroll
    for (int ib = 0; ib < 4; ib++){ acc[ib][0] = 0u; acc[ib][1] = 0u; }

    issue(0); issue(1);
    const int NST = (GG + CHUNK - 1) / CHUNK;

    for (int s = 0; s < NST; s++){
        asm volatile("cp.async.wait_group 1;" ::: "memory");
        __syncthreads();
        const __nv_bfloat16* rbuf = (const __nv_bfloat16*)(smem + (s & 1) * STAGE_BYTES);
        const int cbase = s * CHUNK;
        const int cells = min(CHUNK, GG - cbase);

        auto body = [&](int ci){
            unsigned c4 = *(const unsigned*)(colors + (cbase + ci)*64 + w*4);
            #pragma unroll
            for (int ib = 0; ib < 4; ib++){
                int c = (c4 >> (8*ib)) & 0xFF;
                uint2 v = *(const uint2*)(rbuf + (ci*NC + c)*HID + q*4);
                acc[ib][0] = bfma2(v.x, ONES, acc[ib][0]);
                acc[ib][1] = bfma2(v.y, ONES, acc[ib][1]);
            }
        };
        if (cells == CHUNK){
            #pragma unroll
            for (int ci = 0; ci < CHUNK; ci++) body(ci);
        } else {
            for (int ci = 0; ci < cells; ci++) body(ci);
        }
        __syncthreads();
        issue(s + 2);
    }

    float bvv[4];
    { float4 bv = *(const float4*)(b1 + q*4); bvv[0]=bv.x; bvv[1]=bv.y; bvv[2]=bv.z; bvv[3]=bv.w; }
    #pragma unroll
    for (int ib = 0; ib < 4; ib++){
        int bg = bblock + w*4 + ib;
        float v0 = gelu_f(blo(acc[ib][0]) + bvv[0]);
        float v1 = gelu_f(bhi(acc[ib][0]) + bvv[1]);
        float v2 = gelu_f(blo(acc[ib][1]) + bvv[2]);
        float v3 = gelu_f(bhi(acc[ib][1]) + bvv[3]);
        *(uint2*)(g_h1b + (size_t)bg*HID + 4*q) = make_uint2(pack_bf2(v0, v1), pack_bf2(v2, v3));
    }
}

/* ---------------------------------------------------------------------- */
/* k_rest: 64 rows/CTA, 8 warps; warp-pairs split N halves per layer.     */
/* ---------------------------------------------------------------------- */
__global__ __launch_bounds__(256) void k_rest(
    const float* __restrict__ gfeat, const float* __restrict__ gum,
    const float* __restrict__ enc_b2, const float* __restrict__ by,
    const float* __restrict__ bz,     const float* __restrict__ rz_b1,
    const float* __restrict__ rz_b2,  const float* __restrict__ ry_b1,
    const float* __restrict__ ry_b2,  const float* __restrict__ sel_b1,
    const float* __restrict__ sel_b2,
    float* __restrict__ out)
{
    extern __shared__ char smem[];
    const int tid = threadIdx.x, lane = tid & 31, warp = tid >> 5;
    const int pair = warp >> 1, h = warp & 1;
    const int t = lane & 3, g = lane >> 2;
    const int b0 = blockIdx.x * 64;
    const uint32_t su = (uint32_t)__cvta_generic_to_shared(smem);
    float* bs = (float*)smem;

    if (tid < 128){
        bs[BO_ENC2 + tid] = enc_b2[tid];
        bs[BO_Y + tid]    = by[tid];
        bs[BO_RY2 + tid]  = ry_b2[tid];
    }
    if (tid < 64){
        bs[BO_Z + tid]    = bz[tid];
        bs[BO_RZ1 + tid]  = rz_b1[tid];
        bs[BO_RZ2 + tid]  = rz_b2[tid];
        bs[BO_RY1 + tid]  = ry_b1[tid];
        bs[BO_SEL1 + tid] = sel_b1[tid];
        bs[BO_SEL2 + tid] = sel_b2[tid];
    }

    /* C0: H1 (64 x 256B -> stride 272) + enc2 */
    for (int i = tid; i < 64*16; i += 256){
        int r = i >> 4, ch = i & 15;
        cp16(su + RS_H1 + r*272 + ch*16, (const char*)g_h1b + (size_t)(b0 + r)*256 + ch*16);
    }
    cpa(su + RS_WD0, (const char*)g_wt + WT_ENC2, 34816, tid, 256);
    CP_COMMIT();
    /* C1: wy */
    cpa(su + RS_WD1, (const char*)g_wt + WT_WY, 34816, tid, 256);
    CP_COMMIT();
    /* C2: persistent refine weights */
    cpa(su + RS_RZ1, (const char*)g_wt + WT_RZ1, 27648, tid, 256);
    cpa(su + RS_RZ2, (const char*)g_wt + WT_RZ2,  9216, tid, 256);
    cpa(su + RS_RY1, (const char*)g_wt + WT_RY1, 27648, tid, 256);
    cpa(su + RS_RY2, (const char*)g_wt + WT_RY2, 18432, tid, 256);
    CP_COMMIT();

    /* gf -> CAT cols 192:207 (byte 384) */
    if (tid < 64){
        const float4* gp = (const float4*)(gfeat + (size_t)(b0 + tid)*16);
        float4 f0 = __ldg(gp), f1 = __ldg(gp+1), f2 = __ldg(gp+2), f3 = __ldg(gp+3);
        char* row = smem + RS_CAT + tid*432 + 384;
        *(uint4*)(row)      = make_uint4(pack_bf2(f0.x,f0.y), pack_bf2(f0.z,f0.w),
                                         pack_bf2(f1.x,f1.y), pack_bf2(f1.z,f1.w));
        *(uint4*)(row + 16) = make_uint4(pack_bf2(f2.x,f2.y), pack_bf2(f2.z,f2.w),
                                         pack_bf2(f3.x,f3.y), pack_bf2(f3.z,f3.w));
    }
    CP_WAIT(2);           /* C0 done */
    __syncthreads();

    /* per-lane fragment addressing */
    const uint32_t arow = (uint32_t)(lane & 15), ahalf = (uint32_t)((lane >> 4) * 16);
    const uint32_t brow = (uint32_t)(((lane >> 4) & 1)*8 + (lane & 7));
    const uint32_t bhalf = (uint32_t)(((lane >> 3) & 1) * 16);
    #define ALANE(base, str) ((base) + arow*(str) + ahalf)
    #define WLANE(base, str) ((base) + brow*(str) + bhalf)
    #define OLC(base, str, coff) ((base) + (uint32_t)g*(str) + (uint32_t)t*4 + (coff)), \
                                 ((base) + (uint32_t)(g+8)*(str) + (uint32_t)t*4 + (coff))

    const uint32_t H1p  = su + RS_H1  + pair*16*272;
    const uint32_t H2p  = su + RS_H2  + pair*16*272;
    const uint32_t CATp = su + RS_CAT + pair*16*432;
    const uint32_t Tp   = su + RS_T   + pair*16*144;

    /* L1: h2 = gelu(h1 @ enc_w2 + b), N=128 split 64/64 */
    layer<8,8,true>(ALANE(H1p,272), WLANE(su+RS_WD0 + h*64*272, 272), 272,
                    bs+BO_ENC2 + h*64, t, OLC(H2p,272,h*128));
    __syncthreads();
    /* C3: wz -> H1 region (dead); C4: sel1 -> WD0 */
    cpa(su + RS_H1,  (const char*)g_wt + WT_WZ,   17408, tid, 256); CP_COMMIT();
    cpa(su + RS_WD0, (const char*)g_wt + WT_SEL1, 17408, tid, 256); CP_COMMIT();
    CP_WAIT(3);           /* C1 (wy) done */
    __syncthreads();

    /* L2: y -> CAT cols 0:127 */
    layer<8,8,false>(ALANE(H2p,272), WLANE(su+RS_WD1 + h*64*272, 272), 272,
                     bs+BO_Y + h*64, t, OLC(CATp,432,h*128));
    CP_WAIT(1);           /* C2 + C3 done */
    __syncthreads();
    /* L3: z -> CAT cols 128:191 (byte 256) */
    layer<8,4,false>(ALANE(H2p,272), WLANE(su+RS_H1 + h*32*272, 272), 272,
                     bs+BO_Z + h*32, t, OLC(CATp+256,432,h*64));
    __syncthreads();
    /* C5: sel2 -> WD1 (wy dead) */
    cpa(su + RS_WD1, (const char*)g_wt + WT_SEL2, 9216, tid, 256); CP_COMMIT();

    /* refinement cycles */
    #pragma unroll 1
    for (int cyc = 0; cyc < 3; cyc++){
        layer<13,4,true >(ALANE(CATp,432), WLANE(su+RS_RZ1 + h*32*432, 432), 432,
                          bs+BO_RZ1 + h*32, t, OLC(Tp,144,h*64));
        __syncthreads();
        layer<4, 4,false>(ALANE(Tp,144),   WLANE(su+RS_RZ2 + h*32*144, 144), 144,
                          bs+BO_RZ2 + h*32, t, OLC(CATp+256,432,h*64));
        __syncthreads();
        layer<13,4,true >(ALANE(CATp,432), WLANE(su+RS_RY1 + h*32*432, 432), 432,
                          bs+BO_RY1 + h*32, t, OLC(Tp,144,h*64));
        __syncthreads();
        layer<4, 8,false>(ALANE(Tp,144),   WLANE(su+RS_RY2 + h*64*144, 144), 144,
                          bs+BO_RY2 + h*64, t, OLC(CATp,432,h*128));
        __syncthreads();
    }

    CP_WAIT(1);           /* C4 (sel1) done */
    /* sel1: A = CAT cols 0:128 */
    layer<8,4,true>(ALANE(CATp,432), WLANE(su+RS_WD0 + h*32*272, 272), 272,
                    bs+BO_SEL1 + h*32, t, OLC(Tp,144,h*64));
    CP_WAIT(0);
    __syncthreads();

    /* sel2 -> f32 logits into CAT region (free), then block softmax */
    {
        float acc[4][4];
        initacc<4>(acc, bs + BO_SEL2 + h*32, t);
        gemm<4,4>(acc, ALANE(Tp,144), WLANE(su+RS_WD1 + h*32*144, 144), 144);
        float* LG = (float*)(smem + RS_CAT);
        int r0l = pair*16 + g;
        #pragma unroll
        for (int nt = 0; nt < 4; nt++){
            int c = h*32 + nt*8 + 2*t;
            LG[r0l*64 + c]       = acc[nt][0];
            LG[r0l*64 + c + 1]   = acc[nt][1];
            LG[(r0l+8)*64 + c]   = acc[nt][2];
            LG[(r0l+8)*64 + c+1] = acc[nt][3];
        }
    }
    __syncthreads();
    {
        const float* LG = (const float*)(smem + RS_CAT);
        int r = warp*8 + (lane >> 2);
        int c0 = (lane & 3) * 16;
        int bg = b0 + r;
        float v[16];
        #pragma unroll
        for (int j = 0; j < 16; j += 4){
            float4 gv = *(const float4*)(gum + (size_t)bg*64 + c0 + j);
            v[j]   = LG[r*64 + c0 + j]     + gv.x;
            v[j+1] = LG[r*64 + c0 + j + 1] + gv.y;
            v[j+2] = LG[r*64 + c0 + j + 2] + gv.z;
            v[j+3] = LG[r*64 + c0 + j + 3] + gv.w;
        }
        float m = v[0];
        #pragma unroll
        for (int j = 1; j < 16; j++) m = fmaxf(m, v[j]);
        m = fmaxf(m, __shfl_xor_sync(0xffffffffu, m, 1));
        m = fmaxf(m, __shfl_xor_sync(0xffffffffu, m, 2));
        float s = 0.0f;
        #pragma unroll
        for (int j = 0; j < 16; j++){ v[j] = expf(v[j] - m); s += v[j]; }
        s += __shfl_xor_sync(0xffffffffu, s, 1);
        s += __shfl_xor_sync(0xffffffffu, s, 2);
        float inv = 1.0f / s;
        #pragma unroll
        for (int j = 0; j < 16; j += 4){
            *(float4*)(out + (size_t)bg*64 + c0 + j) =
                make_float4(v[j]*inv, v[j+1]*inv, v[j+2]*inv, v[j+3]*inv);
        }
    }
    #undef ALANE
    #undef WLANE
    #undef OLC
}

/* ---------------------------------------------------------------------- */
extern "C" void kernel_launch(void* const* d_in, const int* in_sizes, int n_in,
                              void* d_out, int out_size){
    const unsigned int* grid32 = (const unsigned int*)d_in[0];
    const float* gfeat  = (const float*)d_in[1];
    const float* gum    = (const float*)d_in[2];
    const float* enc_w1 = (const float*)d_in[3];
    const float* enc_b1 = (const float*)d_in[4];
    const float* enc_w2 = (const float*)d_in[5];
    const float* enc_b2 = (const float*)d_in[6];
    const float* wy     = (const float*)d_in[7];
    const float* by     = (const float*)d_in[8];
    const float* wz     = (const float*)d_in[9];
    const float* bz     = (const float*)d_in[10];
    const float* rz_w1  = (const float*)d_in[11];
    const float* rz_b1  = (const float*)d_in[12];
    const float* rz_w2  = (const float*)d_in[13];
    const float* rz_b2  = (const float*)d_in[14];
    const float* ry_w1  = (const float*)d_in[15];
    const float* ry_b1  = (const float*)d_in[16];
    const float* ry_w2  = (const float*)d_in[17];
    const float* ry_b2  = (const float*)d_in[18];
    const float* sel_w1 = (const float*)d_in[19];
    const float* sel_b1 = (const float*)d_in[20];
    const float* sel_w2 = (const float*)d_in[21];
    const float* sel_b2 = (const float*)d_in[22];
    float* out = (float*)d_out;

    cudaFuncSetAttribute(k_enc1, cudaFuncAttributeMaxDynamicSharedMemorySize, ENC1_SMEM);
    cudaFuncSetAttribute(k_rest, cudaFuncAttributeMaxDynamicSharedMemorySize, RS_TOTAL);

    k_detect<<<1, 32>>>(grid32);
    k_prep<<<2048, 256>>>(enc_w1, grid32, enc_w2, wy, wz, rz_w1, rz_w2, ry_w1, ry_w2, sel_w1, sel_w2);
    k_enc1<<<BB/64, 512, ENC1_SMEM>>>(enc_b1);
    k_rest<<<BB/64, 256, RS_TOTAL>>>(gfeat, gum,
        enc_b2, by, bz, rz_b1, rz_b2, ry_b1, ry_b2, sel_b1, sel_b2, out);
    (void)in_sizes; (void)n_in; (void)out_size;
}

// round 10
// speedup vs baseline: 3.0965x; 1.4139x over previous
#include <cuda_runtime.h>
#include <cuda_bf16.h>
#include <cuda_fp16.h>
#include <stdint.h>

#define BB   8192
#define GG   900
#define NC   10
#define HID  128

/* ---- enc1 staging: e5m2 weights, 16-cell chunks, 32-batch blocks ---- */
#define CHUNK 16
#define ROWB  (NC*HID)              /* 1280 B per cell (e5m2) */
#define STAGE_BYTES (CHUNK*ROWB)    /* 20480 */
#define COLORS_OFF  (2*STAGE_BYTES) /* 40960 */
#define ENC1_SMEM   (COLORS_OFF + 32*GG)   /* 69760 */

/* ---- transposed padded weight blob W^T[N][K+8] bf16 (byte offsets) ---- */
#define WT_ENC2 0        /* 128 x 136 = 34816 */
#define WT_WY   34816
#define WT_WZ   69632    /* 64 x 136 = 17408 */
#define WT_RZ1  87040    /* 64 x 216 = 27648 */
#define WT_RZ2  114688   /* 64 x 72  = 9216  */
#define WT_RY1  123904
#define WT_RY2  151552   /* 128 x 72 = 18432 */
#define WT_SEL1 169984
#define WT_SEL2 187392
#define WT_TOTAL 196608

/* ---- k_rest SMEM (bytes) ---- */
#define RS_BIAS 0
#define RS_H1   3072
#define RS_H2   20480
#define RS_CAT  37888
#define RS_T    65536
#define RS_WD0  74752
#define RS_WD1  109568
#define RS_RZ1  144384
#define RS_RZ2  172032
#define RS_RY1  181248
#define RS_RY2  208896
#define RS_TOTAL 227328

#define BO_ENC2 0
#define BO_Y    128
#define BO_Z    256
#define BO_RZ1  320
#define BO_RZ2  384
#define BO_RY1  448
#define BO_RY2  512
#define BO_SEL1 640
#define BO_SEL2 704

static __device__ __align__(16) unsigned char g_w1e[GG*NC*HID];   /* e5m2 enc_w1 */
static __device__ __align__(16) __nv_bfloat16 g_wt[WT_TOTAL/2];
static __device__ __align__(16) __nv_bfloat16 g_h1b[(size_t)BB*HID];
static __device__ __align__(16) unsigned char g_colors[BB*GG];
static __device__ int g_is64;

__device__ __forceinline__ float gelu_f(float x){
    return 0.5f * x * (1.0f + erff(x * 0.7071067811865476f));
}
__device__ __forceinline__ unsigned pack_bf2(float lo, float hi){
    unsigned d; asm("cvt.rn.bf16x2.f32 %0, %1, %2;" : "=r"(d) : "f"(hi), "f"(lo)); return d;
}
__device__ __forceinline__ unsigned hfma2(unsigned a, unsigned b, unsigned c){
    unsigned d; asm("fma.rn.f16x2 %0, %1, %2, %3;" : "=r"(d) : "r"(a), "r"(b), "r"(c)); return d;
}
__device__ __forceinline__ unsigned prmt(unsigned v, unsigned sel){
    unsigned d; asm("prmt.b32 %0, %1, 0, %2;" : "=r"(d) : "r"(v), "r"(sel)); return d;
}

#define CP_COMMIT() asm volatile("cp.async.commit_group;" ::: "memory")
#define CP_WAIT(N)  asm volatile("cp.async.wait_group %0;" :: "n"(N) : "memory")

__device__ __forceinline__ void cp16(uint32_t d, const void* s){
    asm volatile("cp.async.ca.shared.global [%0], [%1], 16;" :: "r"(d), "l"(s));
}
__device__ __forceinline__ void cpa(uint32_t dst, const void* src, int bytes, int tid, int nthr){
    const char* s = (const char*)src;
    for (int off = tid*16; off < bytes; off += nthr*16) cp16(dst + off, s + off);
}

/* ---- mma.sync / ldmatrix ---- */
__device__ __forceinline__ uint4 ldm4(uint32_t a){
    uint4 r;
    asm volatile("ldmatrix.sync.aligned.m8n8.x4.shared.b16 {%0,%1,%2,%3}, [%4];"
        : "=r"(r.x), "=r"(r.y), "=r"(r.z), "=r"(r.w) : "r"(a));
    return r;
}
__device__ __forceinline__ void mma16816(float (&c)[4], const uint4& a, uint32_t b0, uint32_t b1){
    asm volatile("mma.sync.aligned.m16n8k16.row.col.f32.bf16.bf16.f32 "
        "{%0,%1,%2,%3},{%4,%5,%6,%7},{%8,%9},{%0,%1,%2,%3};"
        : "+f"(c[0]), "+f"(c[1]), "+f"(c[2]), "+f"(c[3])
        : "r"(a.x), "r"(a.y), "r"(a.z), "r"(a.w), "r"(b0), "r"(b1));
}

template<int KS, int NT>
__device__ __forceinline__ void gemm(float (&acc)[NT][4], uint32_t aLane, uint32_t wLane, int wStr){
    #pragma unroll
    for (int ks = 0; ks < KS; ks++){
        uint4 A = ldm4(aLane + ks*32);
        #pragma unroll
        for (int p = 0; p < NT/2; p++){
            uint4 B = ldm4(wLane + p*16*wStr + ks*32);
            mma16816(acc[2*p],   A, B.x, B.y);
            mma16816(acc[2*p+1], A, B.z, B.w);
        }
    }
}
template<int NT>
__device__ __forceinline__ void initacc(float (&acc)[NT][4], const float* bias, int t){
    #pragma unroll
    for (int nt = 0; nt < NT; nt++){
        float b0 = bias[nt*8 + 2*t], b1 = bias[nt*8 + 2*t + 1];
        acc[nt][0] = b0; acc[nt][1] = b1; acc[nt][2] = b0; acc[nt][3] = b1;
    }
}
template<int NT, bool ACT>
__device__ __forceinline__ void storeacc(float (&acc)[NT][4], uint32_t oL0, uint32_t oL1){
    #pragma unroll
    for (int nt = 0; nt < NT; nt++){
        float v0 = acc[nt][0], v1 = acc[nt][1], v2 = acc[nt][2], v3 = acc[nt][3];
        if (ACT){ v0 = gelu_f(v0); v1 = gelu_f(v1); v2 = gelu_f(v2); v3 = gelu_f(v3); }
        unsigned u0 = pack_bf2(v0, v1), u1 = pack_bf2(v2, v3);
        asm volatile("st.shared.b32 [%0], %1;" :: "r"(oL0 + nt*16), "r"(u0));
        asm volatile("st.shared.b32 [%0], %1;" :: "r"(oL1 + nt*16), "r"(u1));
    }
}
template<int KS, int NT, bool ACT>
__device__ __forceinline__ void layer(uint32_t aLane, uint32_t wLane, int wStr,
                                      const float* bias, int t, uint32_t oL0, uint32_t oL1){
    float acc[NT][4];
    initacc<NT>(acc, bias, t);
    gemm<KS, NT>(acc, aLane, wLane, wStr);
    storeacc<NT, ACT>(acc, oL0, oL1);
}

/* ---------------------------------------------------------------------- */
__global__ void k_detect(const unsigned int* __restrict__ g32){
    unsigned v = 0;
    if (threadIdx.x < 16) v = g32[2*threadIdx.x + 1];
    unsigned any = __ballot_sync(0xffffffffu, v != 0u);
    if (threadIdx.x == 0) g_is64 = (any == 0u) ? 1 : 0;
}

__device__ void build_wt(__nv_bfloat16* dst, const float* __restrict__ W, int N, int K, int Kp,
                         int mode, int t, int stride){
    int total = N * K;
    for (int idx = t; idx < total; idx += stride){
        int n = idx / K, k = idx - n*K;
        int src = k;
        if (mode == 1) src = (k < 128) ? (64 + k) : ((k < 192) ? (k - 128) : k);
        dst[(size_t)n*Kp + k] = __float2bfloat16(W[(size_t)src*N + n]);
    }
}

__global__ void k_prep(const float* __restrict__ w1, const unsigned int* __restrict__ g32,
                       const float* __restrict__ enc_w2, const float* __restrict__ wy,
                       const float* __restrict__ wz,     const float* __restrict__ rz_w1,
                       const float* __restrict__ rz_w2,  const float* __restrict__ ry_w1,
                       const float* __restrict__ ry_w2,  const float* __restrict__ sel_w1,
                       const float* __restrict__ sel_w2){
    const int stride = gridDim.x * blockDim.x;
    const int t = blockIdx.x * blockDim.x + threadIdx.x;
    /* w1 -> e5m2, 4 values per u32 store */
    {
        const float4* s = (const float4*)w1;
        unsigned* d = (unsigned*)g_w1e;
        for (int i = t; i < GG*NC*HID/4; i += stride){
            float4 v = s[i];
            unsigned short a, b;
            asm("cvt.rn.satfinite.e5m2x2.f32 %0, %1, %2;" : "=h"(a) : "f"(v.y), "f"(v.x));
            asm("cvt.rn.satfinite.e5m2x2.f32 %0, %1, %2;" : "=h"(b) : "f"(v.w), "f"(v.z));
            d[i] = (unsigned)a | ((unsigned)b << 16);
        }
    }
    build_wt(g_wt + WT_ENC2/2, enc_w2, 128, 128, 136, 0, t, stride);
    build_wt(g_wt + WT_WY/2,   wy,     128, 128, 136, 0, t, stride);
    build_wt(g_wt + WT_WZ/2,   wz,      64, 128, 136, 0, t, stride);
    build_wt(g_wt + WT_RZ1/2,  rz_w1,   64, 208, 216, 0, t, stride);
    build_wt(g_wt + WT_RZ2/2,  rz_w2,   64,  64,  72, 0, t, stride);
    build_wt(g_wt + WT_RY1/2,  ry_w1,   64, 208, 216, 1, t, stride);
    build_wt(g_wt + WT_RY2/2,  ry_w2,  128,  64,  72, 0, t, stride);
    build_wt(g_wt + WT_SEL1/2, sel_w1,  64, 128, 136, 0, t, stride);
    build_wt(g_wt + WT_SEL2/2, sel_w2,  64,  64,  72, 0, t, stride);
    const int is64 = g_is64;
    uchar4* cd = (uchar4*)g_colors;
    if (is64){
        const ulonglong2* gp = (const ulonglong2*)g32;
        for (int i = t; i < BB*GG/4; i += stride){
            ulonglong2 a = gp[2*i], b = gp[2*i+1];
            cd[i] = make_uchar4((unsigned char)a.x, (unsigned char)a.y,
                                (unsigned char)b.x, (unsigned char)b.y);
        }
    } else {
        const uint4* gp = (const uint4*)g32;
        for (int i = t; i < BB*GG/4; i += stride){
            uint4 v = gp[i];
            cd[i] = make_uchar4((unsigned char)v.x, (unsigned char)v.y,
                                (unsigned char)v.z, (unsigned char)v.w);
        }
    }
}

/* ---------------------------------------------------------------------- */
/* Encoder layer 1: e5m2 weights, PRMT-expand to half2, fp16 accumulate.  */
/* 32 batches/block, 256 threads (8 warps x 4 batches), 16 hid/thread.    */
/* ---------------------------------------------------------------------- */
__global__ __launch_bounds__(256) void k_enc1(const float* __restrict__ b1){
    extern __shared__ char smem[];
    unsigned char* colors = (unsigned char*)(smem + COLORS_OFF);
    const int tid = threadIdx.x;
    const int lane = tid & 31, w = tid >> 5;       /* w: 0..7 */
    const int q = lane & 7, bt = lane >> 3;        /* q: hid octet, bt: batch in warp */
    const int bblock = blockIdx.x * 32;
    const unsigned ONESH = 0x3C003C00u;

    /* colors tile transposed: [cell][32] */
    for (int idx = tid; idx < 32*GG; idx += 256){
        int bl = idx / GG, cell = idx - bl*GG;
        colors[cell*32 + bl] = g_colors[(bblock + bl)*GG + cell];
    }

    const unsigned smem_s = (unsigned)__cvta_generic_to_shared(smem);
    const char* wsrc = (const char*)g_w1e;

    auto issue = [&](int s){
        int base = s * CHUNK;
        if (base < GG){
            int cells = min(CHUNK, GG - base);
            int bytes = cells * ROWB;
            unsigned dbase = smem_s + (s & 1) * STAGE_BYTES;
            const char* sbase = wsrc + (size_t)base * ROWB;
            for (int off = tid*16; off < bytes; off += 256*16) cp16(dbase + off, sbase + off);
        }
        CP_COMMIT();
    };

    unsigned acc[8];
    #pragma unroll
    for (int k = 0; k < 8; k++) acc[k] = 0u;

    issue(0); issue(1);
    const int NST = (GG + CHUNK - 1) / CHUNK;

    for (int s = 0; s < NST; s++){
        asm volatile("cp.async.wait_group 1;" ::: "memory");
        __syncthreads();
        const char* rbuf = smem + (s & 1) * STAGE_BYTES;
        const int cbase = s * CHUNK;
        const int cells = min(CHUNK, GG - cbase);

        auto body = [&](int ci){
            unsigned c4 = *(const unsigned*)(colors + (cbase + ci)*32 + w*4);
            unsigned c = (c4 >> (8*bt)) & 0xFFu;
            uint4 v = *(const uint4*)(rbuf + ci*ROWB + c*HID + q*16);
            acc[0] = hfma2(prmt(v.x, 0x1404u), ONESH, acc[0]);
            acc[1] = hfma2(prmt(v.x, 0x3424u), ONESH, acc[1]);
            acc[2] = hfma2(prmt(v.y, 0x1404u), ONESH, acc[2]);
            acc[3] = hfma2(prmt(v.y, 0x3424u), ONESH, acc[3]);
            acc[4] = hfma2(prmt(v.z, 0x1404u), ONESH, acc[4]);
            acc[5] = hfma2(prmt(v.z, 0x3424u), ONESH, acc[5]);
            acc[6] = hfma2(prmt(v.w, 0x1404u), ONESH, acc[6]);
            acc[7] = hfma2(prmt(v.w, 0x3424u), ONESH, acc[7]);
        };
        if (cells == CHUNK){
            #pragma unroll
            for (int ci = 0; ci < CHUNK; ci++) body(ci);
        } else {
            for (int ci = 0; ci < cells; ci++) body(ci);
        }
        __syncthreads();
        issue(s + 2);
    }

    /* epilogue: +bias, gelu, write bf16 h1 row-major */
    {
        const int bg = bblock + w*4 + bt;
        unsigned pk[8];
        #pragma unroll
        for (int k = 0; k < 8; k++){
            __half2 h = *(const __half2*)&acc[k];
            float f0 = __low2float(h)  + __ldg(b1 + q*16 + 2*k);
            float f1 = __high2float(h) + __ldg(b1 + q*16 + 2*k + 1);
            pk[k] = pack_bf2(gelu_f(f0), gelu_f(f1));
        }
        uint4* dst = (uint4*)(g_h1b + (size_t)bg*HID + q*16);
        dst[0] = make_uint4(pk[0], pk[1], pk[2], pk[3]);
        dst[1] = make_uint4(pk[4], pk[5], pk[6], pk[7]);
    }
}

/* ---------------------------------------------------------------------- */
/* k_rest: unchanged from Round 9 (26 us).                                */
/* ---------------------------------------------------------------------- */
__global__ __launch_bounds__(256) void k_rest(
    const float* __restrict__ gfeat, const float* __restrict__ gum,
    const float* __restrict__ enc_b2, const float* __restrict__ by,
    const float* __restrict__ bz,     const float* __restrict__ rz_b1,
    const float* __restrict__ rz_b2,  const float* __restrict__ ry_b1,
    const float* __restrict__ ry_b2,  const float* __restrict__ sel_b1,
    const float* __restrict__ sel_b2,
    float* __restrict__ out)
{
    extern __shared__ char smem[];
    const int tid = threadIdx.x, lane = tid & 31, warp = tid >> 5;
    const int pair = warp >> 1, h = warp & 1;
    const int t = lane & 3, g = lane >> 2;
    const int b0 = blockIdx.x * 64;
    const uint32_t su = (uint32_t)__cvta_generic_to_shared(smem);
    float* bs = (float*)smem;

    if (tid < 128){
        bs[BO_ENC2 + tid] = enc_b2[tid];
        bs[BO_Y + tid]    = by[tid];
        bs[BO_RY2 + tid]  = ry_b2[tid];
    }
    if (tid < 64){
        bs[BO_Z + tid]    = bz[tid];
        bs[BO_RZ1 + tid]  = rz_b1[tid];
        bs[BO_RZ2 + tid]  = rz_b2[tid];
        bs[BO_RY1 + tid]  = ry_b1[tid];
        bs[BO_SEL1 + tid] = sel_b1[tid];
        bs[BO_SEL2 + tid] = sel_b2[tid];
    }

    for (int i = tid; i < 64*16; i += 256){
        int r = i >> 4, ch = i & 15;
        cp16(su + RS_H1 + r*272 + ch*16, (const char*)g_h1b + (size_t)(b0 + r)*256 + ch*16);
    }
    cpa(su + RS_WD0, (const char*)g_wt + WT_ENC2, 34816, tid, 256);
    CP_COMMIT();
    cpa(su + RS_WD1, (const char*)g_wt + WT_WY, 34816, tid, 256);
    CP_COMMIT();
    cpa(su + RS_RZ1, (const char*)g_wt + WT_RZ1, 27648, tid, 256);
    cpa(su + RS_RZ2, (const char*)g_wt + WT_RZ2,  9216, tid, 256);
    cpa(su + RS_RY1, (const char*)g_wt + WT_RY1, 27648, tid, 256);
    cpa(su + RS_RY2, (const char*)g_wt + WT_RY2, 18432, tid, 256);
    CP_COMMIT();

    if (tid < 64){
        const float4* gp = (const float4*)(gfeat + (size_t)(b0 + tid)*16);
        float4 f0 = __ldg(gp), f1 = __ldg(gp+1), f2 = __ldg(gp+2), f3 = __ldg(gp+3);
        char* row = smem + RS_CAT + tid*432 + 384;
        *(uint4*)(row)      = make_uint4(pack_bf2(f0.x,f0.y), pack_bf2(f0.z,f0.w),
                                         pack_bf2(f1.x,f1.y), pack_bf2(f1.z,f1.w));
        *(uint4*)(row + 16) = make_uint4(pack_bf2(f2.x,f2.y), pack_bf2(f2.z,f2.w),
                                         pack_bf2(f3.x,f3.y), pack_bf2(f3.z,f3.w));
    }
    CP_WAIT(2);
    __syncthreads();

    const uint32_t arow = (uint32_t)(lane & 15), ahalf = (uint32_t)((lane >> 4) * 16);
    const uint32_t brow = (uint32_t)(((lane >> 4) & 1)*8 + (lane & 7));
    const uint32_t bhalf = (uint32_t)(((lane >> 3) & 1) * 16);
    #define ALANE(base, str) ((base) + arow*(str) + ahalf)
    #define WLANE(base, str) ((base) + brow*(str) + bhalf)
    #define OLC(base, str, coff) ((base) + (uint32_t)g*(str) + (uint32_t)t*4 + (coff)), \
                                 ((base) + (uint32_t)(g+8)*(str) + (uint32_t)t*4 + (coff))

    const uint32_t H1p  = su + RS_H1  + pair*16*272;
    const uint32_t H2p  = su + RS_H2  + pair*16*272;
    const uint32_t CATp = su + RS_CAT + pair*16*432;
    const uint32_t Tp   = su + RS_T   + pair*16*144;

    layer<8,8,true>(ALANE(H1p,272), WLANE(su+RS_WD0 + h*64*272, 272), 272,
                    bs+BO_ENC2 + h*64, t, OLC(H2p,272,h*128));
    __syncthreads();
    cpa(su + RS_H1,  (const char*)g_wt + WT_WZ,   17408, tid, 256); CP_COMMIT();
    cpa(su + RS_WD0, (const char*)g_wt + WT_SEL1, 17408, tid, 256); CP_COMMIT();
    CP_WAIT(3);
    __syncthreads();

    layer<8,8,false>(ALANE(H2p,272), WLANE(su+RS_WD1 + h*64*272, 272), 272,
                     bs+BO_Y + h*64, t, OLC(CATp,432,h*128));
    CP_WAIT(1);
    __syncthreads();
    layer<8,4,false>(ALANE(H2p,272), WLANE(su+RS_H1 + h*32*272, 272), 272,
                     bs+BO_Z + h*32, t, OLC(CATp+256,432,h*64));
    __syncthreads();
    cpa(su + RS_WD1, (const char*)g_wt + WT_SEL2, 9216, tid, 256); CP_COMMIT();

    #pragma unroll 1
    for (int cyc = 0; cyc < 3; cyc++){
        layer<13,4,true >(ALANE(CATp,432), WLANE(su+RS_RZ1 + h*32*432, 432), 432,
                          bs+BO_RZ1 + h*32, t, OLC(Tp,144,h*64));
        __syncthreads();
        layer<4, 4,false>(ALANE(Tp,144),   WLANE(su+RS_RZ2 + h*32*144, 144), 144,
                          bs+BO_RZ2 + h*32, t, OLC(CATp+256,432,h*64));
        __syncthreads();
        layer<13,4,true >(ALANE(CATp,432), WLANE(su+RS_RY1 + h*32*432, 432), 432,
                          bs+BO_RY1 + h*32, t, OLC(Tp,144,h*64));
        __syncthreads();
        layer<4, 8,false>(ALANE(Tp,144),   WLANE(su+RS_RY2 + h*64*144, 144), 144,
                          bs+BO_RY2 + h*64, t, OLC(CATp,432,h*128));
        __syncthreads();
    }

    CP_WAIT(1);
    layer<8,4,true>(ALANE(CATp,432), WLANE(su+RS_WD0 + h*32*272, 272), 272,
                    bs+BO_SEL1 + h*32, t, OLC(Tp,144,h*64));
    CP_WAIT(0);
    __syncthreads();

    {
        float acc[4][4];
        initacc<4>(acc, bs + BO_SEL2 + h*32, t);
        gemm<4,4>(acc, ALANE(Tp,144), WLANE(su+RS_WD1 + h*32*144, 144), 144);
        float* LG = (float*)(smem + RS_CAT);
        int r0l = pair*16 + g;
        #pragma unroll
        for (int nt = 0; nt < 4; nt++){
            int c = h*32 + nt*8 + 2*t;
            LG[r0l*64 + c]       = acc[nt][0];
            LG[r0l*64 + c + 1]   = acc[nt][1];
            LG[(r0l+8)*64 + c]   = acc[nt][2];
            LG[(r0l+8)*64 + c+1] = acc[nt][3];
        }
    }
    __syncthreads();
    {
        const float* LG = (const float*)(smem + RS_CAT);
        int r = warp*8 + (lane >> 2);
        int c0 = (lane & 3) * 16;
        int bg = b0 + r;
        float v[16];
        #pragma unroll
        for (int j = 0; j < 16; j += 4){
            float4 gv = *(const float4*)(gum + (size_t)bg*64 + c0 + j);
            v[j]   = LG[r*64 + c0 + j]     + gv.x;
            v[j+1] = LG[r*64 + c0 + j + 1] + gv.y;
            v[j+2] = LG[r*64 + c0 + j + 2] + gv.z;
            v[j+3] = LG[r*64 + c0 + j + 3] + gv.w;
        }
        float m = v[0];
        #pragma unroll
        for (int j = 1; j < 16; j++) m = fmaxf(m, v[j]);
        m = fmaxf(m, __shfl_xor_sync(0xffffffffu, m, 1));
        m = fmaxf(m, __shfl_xor_sync(0xffffffffu, m, 2));
        float s = 0.0f;
        #pragma unroll
        for (int j = 0; j < 16; j++){ v[j] = expf(v[j] - m); s += v[j]; }
        s += __shfl_xor_sync(0xffffffffu, s, 1);
        s += __shfl_xor_sync(0xffffffffu, s, 2);
        float inv = 1.0f / s;
        #pragma unroll
        for (int j = 0; j < 16; j += 4){
            *(float4*)(out + (size_t)bg*64 + c0 + j) =
                make_float4(v[j]*inv, v[j+1]*inv, v[j+2]*inv, v[j+3]*inv);
        }
    }
    #undef ALANE
    #undef WLANE
    #undef OLC
}

/* ---------------------------------------------------------------------- */
extern "C" void kernel_launch(void* const* d_in, const int* in_sizes, int n_in,
                              void* d_out, int out_size){
    const unsigned int* grid32 = (const unsigned int*)d_in[0];
    const float* gfeat  = (const float*)d_in[1];
    const float* gum    = (const float*)d_in[2];
    const float* enc_w1 = (const float*)d_in[3];
    const float* enc_b1 = (const float*)d_in[4];
    const float* enc_w2 = (const float*)d_in[5];
    const float* enc_b2 = (const float*)d_in[6];
    const float* wy     = (const float*)d_in[7];
    const float* by     = (const float*)d_in[8];
    const float* wz     = (const float*)d_in[9];
    const float* bz     = (const float*)d_in[10];
    const float* rz_w1  = (const float*)d_in[11];
    const float* rz_b1  = (const float*)d_in[12];
    const float* rz_w2  = (const float*)d_in[13];
    const float* rz_b2  = (const float*)d_in[14];
    const float* ry_w1  = (const float*)d_in[15];
    const float* ry_b1  = (const float*)d_in[16];
    const float* ry_w2  = (const float*)d_in[17];
    const float* ry_b2  = (const float*)d_in[18];
    const float* sel_w1 = (const float*)d_in[19];
    const float* sel_b1 = (const float*)d_in[20];
    const float* sel_w2 = (const float*)d_in[21];
    const float* sel_b2 = (const float*)d_in[22];
    float* out = (float*)d_out;

    cudaFuncSetAttribute(k_enc1, cudaFuncAttributeMaxDynamicSharedMemorySize, ENC1_SMEM);
    cudaFuncSetAttribute(k_rest, cudaFuncAttributeMaxDynamicSharedMemorySize, RS_TOTAL);

    k_detect<<<1, 32>>>(grid32);
    k_prep<<<2048, 256>>>(enc_w1, grid32, enc_w2, wy, wz, rz_w1, rz_w2, ry_w1, ry_w2, sel_w1, sel_w2);
    k_enc1<<<BB/32, 256, ENC1_SMEM>>>(enc_b1);
    k_rest<<<BB/64, 256, RS_TOTAL>>>(gfeat, gum,
        enc_b2, by, bz, rz_b1, rz_b2, ry_b1, ry_b2, sel_b1, sel_b2, out);
    (void)in_sizes; (void)n_in; (void)out_size;
}

// round 11
// speedup vs baseline: 3.4000x; 1.0980x over previous
#include <cuda_runtime.h>
#include <cuda_bf16.h>
#include <cuda_fp16.h>
#include <stdint.h>

#define BB   8192
#define GG   900
#define NC   10
#define HID  128

/* ---- enc1 staging: e5m2 weights, 16-cell chunks, 64-batch blocks ---- */
#define E1_CHUNK 16
#define E1_ROWB  (NC*HID)             /* 1280 B per cell (e5m2) */
#define E1_STAGE (E1_CHUNK*E1_ROWB)   /* 20480 */
#define E1_COLORS (2*E1_STAGE)        /* 40960 */
#define E1_CPAD  912
#define ENC1_SMEM (E1_COLORS + 64*E1_CPAD)   /* 99328 */

/* ---- transposed padded weight blob W^T[N][K+8] bf16 (byte offsets) ---- */
#define WT_ENC2 0
#define WT_WY   34816
#define WT_WZ   69632
#define WT_RZ1  87040
#define WT_RZ2  114688
#define WT_RY1  123904
#define WT_RY2  151552
#define WT_SEL1 169984
#define WT_SEL2 187392
#define WT_TOTAL 196608

/* ---- k_rest SMEM (bytes) ---- */
#define RS_BIAS 0
#define RS_H1   3072
#define RS_H2   20480
#define RS_CAT  37888
#define RS_T    65536
#define RS_WD0  74752
#define RS_WD1  109568
#define RS_RZ1  144384
#define RS_RZ2  172032
#define RS_RY1  181248
#define RS_RY2  208896
#define RS_TOTAL 227328

#define BO_ENC2 0
#define BO_Y    128
#define BO_Z    256
#define BO_RZ1  320
#define BO_RZ2  384
#define BO_RY1  448
#define BO_RY2  512
#define BO_SEL1 640
#define BO_SEL2 704

static __device__ __align__(16) unsigned char g_w1e[GG*NC*HID];
static __device__ __align__(16) __nv_bfloat16 g_wt[WT_TOTAL/2];
static __device__ __align__(16) __nv_bfloat16 g_h1b[(size_t)BB*HID];
static __device__ __align__(16) unsigned char g_colors[BB*GG];
static __device__ int g_is64;

__device__ __forceinline__ float gelu_f(float x){
    return 0.5f * x * (1.0f + erff(x * 0.7071067811865476f));
}
__device__ __forceinline__ unsigned pack_bf2(float lo, float hi){
    unsigned d; asm("cvt.rn.bf16x2.f32 %0, %1, %2;" : "=r"(d) : "f"(hi), "f"(lo)); return d;
}
__device__ __forceinline__ unsigned hfma2(unsigned a, unsigned b, unsigned c){
    unsigned d; asm("fma.rn.f16x2 %0, %1, %2, %3;" : "=r"(d) : "r"(a), "r"(b), "r"(c)); return d;
}
__device__ __forceinline__ unsigned prmt(unsigned v, unsigned sel){
    unsigned d; asm("prmt.b32 %0, %1, 0, %2;" : "=r"(d) : "r"(v), "r"(sel)); return d;
}

#define CP_COMMIT() asm volatile("cp.async.commit_group;" ::: "memory")
#define CP_WAIT(N)  asm volatile("cp.async.wait_group %0;" :: "n"(N) : "memory")

__device__ __forceinline__ void cp16(uint32_t d, const void* s){
    asm volatile("cp.async.ca.shared.global [%0], [%1], 16;" :: "r"(d), "l"(s));
}
__device__ __forceinline__ void cpa(uint32_t dst, const void* src, int bytes, int tid, int nthr){
    const char* s = (const char*)src;
    for (int off = tid*16; off < bytes; off += nthr*16) cp16(dst + off, s + off);
}

/* ---- mma.sync / ldmatrix ---- */
__device__ __forceinline__ uint4 ldm4(uint32_t a){
    uint4 r;
    asm volatile("ldmatrix.sync.aligned.m8n8.x4.shared.b16 {%0,%1,%2,%3}, [%4];"
        : "=r"(r.x), "=r"(r.y), "=r"(r.z), "=r"(r.w) : "r"(a));
    return r;
}
__device__ __forceinline__ void mma16816(float (&c)[4], const uint4& a, uint32_t b0, uint32_t b1){
    asm volatile("mma.sync.aligned.m16n8k16.row.col.f32.bf16.bf16.f32 "
        "{%0,%1,%2,%3},{%4,%5,%6,%7},{%8,%9},{%0,%1,%2,%3};"
        : "+f"(c[0]), "+f"(c[1]), "+f"(c[2]), "+f"(c[3])
        : "r"(a.x), "r"(a.y), "r"(a.z), "r"(a.w), "r"(b0), "r"(b1));
}

template<int KS, int NT>
__device__ __forceinline__ void gemm(float (&acc)[NT][4], uint32_t aLane, uint32_t wLane, int wStr){
    #pragma unroll
    for (int ks = 0; ks < KS; ks++){
        uint4 A = ldm4(aLane + ks*32);
        #pragma unroll
        for (int p = 0; p < NT/2; p++){
            uint4 B = ldm4(wLane + p*16*wStr + ks*32);
            mma16816(acc[2*p],   A, B.x, B.y);
            mma16816(acc[2*p+1], A, B.z, B.w);
        }
    }
}
template<int NT>
__device__ __forceinline__ void initacc(float (&acc)[NT][4], const float* bias, int t){
    #pragma unroll
    for (int nt = 0; nt < NT; nt++){
        float b0 = bias[nt*8 + 2*t], b1 = bias[nt*8 + 2*t + 1];
        acc[nt][0] = b0; acc[nt][1] = b1; acc[nt][2] = b0; acc[nt][3] = b1;
    }
}
template<int NT, bool ACT>
__device__ __forceinline__ void storeacc(float (&acc)[NT][4], uint32_t oL0, uint32_t oL1){
    #pragma unroll
    for (int nt = 0; nt < NT; nt++){
        float v0 = acc[nt][0], v1 = acc[nt][1], v2 = acc[nt][2], v3 = acc[nt][3];
        if (ACT){ v0 = gelu_f(v0); v1 = gelu_f(v1); v2 = gelu_f(v2); v3 = gelu_f(v3); }
        unsigned u0 = pack_bf2(v0, v1), u1 = pack_bf2(v2, v3);
        asm volatile("st.shared.b32 [%0], %1;" :: "r"(oL0 + nt*16), "r"(u0));
        asm volatile("st.shared.b32 [%0], %1;" :: "r"(oL1 + nt*16), "r"(u1));
    }
}
template<int KS, int NT, bool ACT>
__device__ __forceinline__ void layer(uint32_t aLane, uint32_t wLane, int wStr,
                                      const float* bias, int t, uint32_t oL0, uint32_t oL1){
    float acc[NT][4];
    initacc<NT>(acc, bias, t);
    gemm<KS, NT>(acc, aLane, wLane, wStr);
    storeacc<NT, ACT>(acc, oL0, oL1);
}

/* ---------------------------------------------------------------------- */
__global__ void k_detect(const unsigned int* __restrict__ g32){
    unsigned v = 0;
    if (threadIdx.x < 16) v = g32[2*threadIdx.x + 1];
    unsigned any = __ballot_sync(0xffffffffu, v != 0u);
    if (threadIdx.x == 0) g_is64 = (any == 0u) ? 1 : 0;
}

__device__ void build_wt(__nv_bfloat16* dst, const float* __restrict__ W, int N, int K, int Kp,
                         int mode, int t, int stride){
    int total = N * K;
    for (int idx = t; idx < total; idx += stride){
        int n = idx / K, k = idx - n*K;
        int src = k;
        if (mode == 1) src = (k < 128) ? (64 + k) : ((k < 192) ? (k - 128) : k);
        dst[(size_t)n*Kp + k] = __float2bfloat16(W[(size_t)src*N + n]);
    }
}

__global__ void k_prep(const float* __restrict__ w1, const unsigned int* __restrict__ g32,
                       const float* __restrict__ enc_w2, const float* __restrict__ wy,
                       const float* __restrict__ wz,     const float* __restrict__ rz_w1,
                       const float* __restrict__ rz_w2,  const float* __restrict__ ry_w1,
                       const float* __restrict__ ry_w2,  const float* __restrict__ sel_w1,
                       const float* __restrict__ sel_w2){
    const int stride = gridDim.x * blockDim.x;
    const int t = blockIdx.x * blockDim.x + threadIdx.x;
    {
        const float4* s = (const float4*)w1;
        unsigned* d = (unsigned*)g_w1e;
        for (int i = t; i < GG*NC*HID/4; i += stride){
            float4 v = s[i];
            unsigned short a, b;
            asm("cvt.rn.satfinite.e5m2x2.f32 %0, %1, %2;" : "=h"(a) : "f"(v.y), "f"(v.x));
            asm("cvt.rn.satfinite.e5m2x2.f32 %0, %1, %2;" : "=h"(b) : "f"(v.w), "f"(v.z));
            d[i] = (unsigned)a | ((unsigned)b << 16);
        }
    }
    build_wt(g_wt + WT_ENC2/2, enc_w2, 128, 128, 136, 0, t, stride);
    build_wt(g_wt + WT_WY/2,   wy,     128, 128, 136, 0, t, stride);
    build_wt(g_wt + WT_WZ/2,   wz,      64, 128, 136, 0, t, stride);
    build_wt(g_wt + WT_RZ1/2,  rz_w1,   64, 208, 216, 0, t, stride);
    build_wt(g_wt + WT_RZ2/2,  rz_w2,   64,  64,  72, 0, t, stride);
    build_wt(g_wt + WT_RY1/2,  ry_w1,   64, 208, 216, 1, t, stride);
    build_wt(g_wt + WT_RY2/2,  ry_w2,  128,  64,  72, 0, t, stride);
    build_wt(g_wt + WT_SEL1/2, sel_w1,  64, 128, 136, 0, t, stride);
    build_wt(g_wt + WT_SEL2/2, sel_w2,  64,  64,  72, 0, t, stride);
    const int is64 = g_is64;
    uchar4* cd = (uchar4*)g_colors;
    if (is64){
        const ulonglong2* gp = (const ulonglong2*)g32;
        for (int i = t; i < BB*GG/4; i += stride){
            ulonglong2 a = gp[2*i], b = gp[2*i+1];
            cd[i] = make_uchar4((unsigned char)a.x, (unsigned char)a.y,
                                (unsigned char)b.x, (unsigned char)b.y);
        }
    } else {
        const uint4* gp = (const uint4*)g32;
        for (int i = t; i < BB*GG/4; i += stride){
            uint4 v = gp[i];
            cd[i] = make_uchar4((unsigned char)v.x, (unsigned char)v.y,
                                (unsigned char)v.z, (unsigned char)v.w);
        }
    }
}

/* ---------------------------------------------------------------------- */
/* Encoder layer 1 v3: e5m2 + PRMT expand, 64 batches/block, 512 thr.     */
/* Per chunk: 1 uint4 color load, 16 batched LDS.128, then 256 MACs/lane. */
/* ---------------------------------------------------------------------- */
__global__ __launch_bounds__(512, 1) void k_enc1(const float* __restrict__ b1){
    extern __shared__ char smem[];
    unsigned char* colors = (unsigned char*)(smem + E1_COLORS);
    const int tid = threadIdx.x;
    const int lane = tid & 31, w = tid >> 5;       /* w: 0..15 */
    const int q = lane & 7, bt = lane >> 3;        /* q: hid octet, bt: batch in warp */
    const int bblock = blockIdx.x * 64;
    const unsigned ONESH = 0x3C003C00u;

    /* colors transposed: [b][cell], row stride E1_CPAD */
    for (int idx = tid; idx < 64*GG; idx += 512){
        int b = idx / GG, cell = idx - b*GG;
        colors[b*E1_CPAD + cell] = g_colors[(size_t)(bblock + b)*GG + cell];
    }

    const unsigned smem_s = (unsigned)__cvta_generic_to_shared(smem);
    const char* wsrc = (const char*)g_w1e;

    auto issue = [&](int s){
        int base = s * E1_CHUNK;
        if (base < GG){
            int cells = min(E1_CHUNK, GG - base);
            int bytes = cells * E1_ROWB;
            unsigned dbase = smem_s + (s & 1) * E1_STAGE;
            const char* sbase = wsrc + (size_t)base * E1_ROWB;
            for (int off = tid*16; off < bytes; off += 512*16) cp16(dbase + off, sbase + off);
        }
        CP_COMMIT();
    };

    unsigned acc[8];
    #pragma unroll
    for (int k = 0; k < 8; k++) acc[k] = 0u;

    issue(0); issue(1);
    const int NST = (GG + E1_CHUNK - 1) / E1_CHUNK;
    const unsigned char* crow = colors + (w*4 + bt)*E1_CPAD;

    for (int s = 0; s < NST; s++){
        asm volatile("cp.async.wait_group 1;" ::: "memory");
        __syncthreads();
        const char* rbuf = smem + (s & 1) * E1_STAGE;
        const int cbase = s * E1_CHUNK;
        const int cells = min(E1_CHUNK, GG - cbase);

        if (cells == E1_CHUNK){
            uint4 cw = *(const uint4*)(crow + cbase);
            unsigned cb[16];
            #pragma unroll
            for (int i = 0; i < 4; i++){
                cb[i]      = (cw.x >> (8*i)) & 0xFFu;
                cb[4 + i]  = (cw.y >> (8*i)) & 0xFFu;
                cb[8 + i]  = (cw.z >> (8*i)) & 0xFFu;
                cb[12 + i] = (cw.w >> (8*i)) & 0xFFu;
            }
            uint4 v[16];
            #pragma unroll
            for (int ci = 0; ci < 16; ci++)
                v[ci] = *(const uint4*)(rbuf + ci*E1_ROWB + cb[ci]*HID + q*16);
            #pragma unroll
            for (int ci = 0; ci < 16; ci++){
                acc[0] = hfma2(prmt(v[ci].x, 0x1404u), ONESH, acc[0]);
                acc[1] = hfma2(prmt(v[ci].x, 0x3424u), ONESH, acc[1]);
                acc[2] = hfma2(prmt(v[ci].y, 0x1404u), ONESH, acc[2]);
                acc[3] = hfma2(prmt(v[ci].y, 0x3424u), ONESH, acc[3]);
                acc[4] = hfma2(prmt(v[ci].z, 0x1404u), ONESH, acc[4]);
                acc[5] = hfma2(prmt(v[ci].z, 0x3424u), ONESH, acc[5]);
                acc[6] = hfma2(prmt(v[ci].w, 0x1404u), ONESH, acc[6]);
                acc[7] = hfma2(prmt(v[ci].w, 0x3424u), ONESH, acc[7]);
            }
        } else {
            for (int ci = 0; ci < cells; ci++){
                unsigned c = crow[cbase + ci];
                uint4 vv = *(const uint4*)(rbuf + ci*E1_ROWB + c*HID + q*16);
                acc[0] = hfma2(prmt(vv.x, 0x1404u), ONESH, acc[0]);
                acc[1] = hfma2(prmt(vv.x, 0x3424u), ONESH, acc[1]);
                acc[2] = hfma2(prmt(vv.y, 0x1404u), ONESH, acc[2]);
                acc[3] = hfma2(prmt(vv.y, 0x3424u), ONESH, acc[3]);
                acc[4] = hfma2(prmt(vv.z, 0x1404u), ONESH, acc[4]);
                acc[5] = hfma2(prmt(vv.z, 0x3424u), ONESH, acc[5]);
                acc[6] = hfma2(prmt(vv.w, 0x1404u), ONESH, acc[6]);
                acc[7] = hfma2(prmt(vv.w, 0x3424u), ONESH, acc[7]);
            }
        }
        __syncthreads();
        issue(s + 2);
    }

    /* epilogue: +bias, gelu, write bf16 h1 row-major */
    {
        const int bg = bblock + w*4 + bt;
        unsigned pk[8];
        #pragma unroll
        for (int k = 0; k < 8; k++){
            __half2 h = *(const __half2*)&acc[k];
            float f0 = __low2float(h)  + __ldg(b1 + q*16 + 2*k);
            float f1 = __high2float(h) + __ldg(b1 + q*16 + 2*k + 1);
            pk[k] = pack_bf2(gelu_f(f0), gelu_f(f1));
        }
        uint4* dst = (uint4*)(g_h1b + (size_t)bg*HID + q*16);
        dst[0] = make_uint4(pk[0], pk[1], pk[2], pk[3]);
        dst[1] = make_uint4(pk[4], pk[5], pk[6], pk[7]);
    }
}

/* ---------------------------------------------------------------------- */
/* k_rest: unchanged from Round 9/10 (26.9 us).                           */
/* ---------------------------------------------------------------------- */
__global__ __launch_bounds__(256) void k_rest(
    const float* __restrict__ gfeat, const float* __restrict__ gum,
    const float* __restrict__ enc_b2, const float* __restrict__ by,
    const float* __restrict__ bz,     const float* __restrict__ rz_b1,
    const float* __restrict__ rz_b2,  const float* __restrict__ ry_b1,
    const float* __restrict__ ry_b2,  const float* __restrict__ sel_b1,
    const float* __restrict__ sel_b2,
    float* __restrict__ out)
{
    extern __shared__ char smem[];
    const int tid = threadIdx.x, lane = tid & 31, warp = tid >> 5;
    const int pair = warp >> 1, h = warp & 1;
    const int t = lane & 3, g = lane >> 2;
    const int b0 = blockIdx.x * 64;
    const uint32_t su = (uint32_t)__cvta_generic_to_shared(smem);
    float* bs = (float*)smem;

    if (tid < 128){
        bs[BO_ENC2 + tid] = enc_b2[tid];
        bs[BO_Y + tid]    = by[tid];
        bs[BO_RY2 + tid]  = ry_b2[tid];
    }
    if (tid < 64){
        bs[BO_Z + tid]    = bz[tid];
        bs[BO_RZ1 + tid]  = rz_b1[tid];
        bs[BO_RZ2 + tid]  = rz_b2[tid];
        bs[BO_RY1 + tid]  = ry_b1[tid];
        bs[BO_SEL1 + tid] = sel_b1[tid];
        bs[BO_SEL2 + tid] = sel_b2[tid];
    }

    for (int i = tid; i < 64*16; i += 256){
        int r = i >> 4, ch = i & 15;
        cp16(su + RS_H1 + r*272 + ch*16, (const char*)g_h1b + (size_t)(b0 + r)*256 + ch*16);
    }
    cpa(su + RS_WD0, (const char*)g_wt + WT_ENC2, 34816, tid, 256);
    CP_COMMIT();
    cpa(su + RS_WD1, (const char*)g_wt + WT_WY, 34816, tid, 256);
    CP_COMMIT();
    cpa(su + RS_RZ1, (const char*)g_wt + WT_RZ1, 27648, tid, 256);
    cpa(su + RS_RZ2, (const char*)g_wt + WT_RZ2,  9216, tid, 256);
    cpa(su + RS_RY1, (const char*)g_wt + WT_RY1, 27648, tid, 256);
    cpa(su + RS_RY2, (const char*)g_wt + WT_RY2, 18432, tid, 256);
    CP_COMMIT();

    if (tid < 64){
        const float4* gp = (const float4*)(gfeat + (size_t)(b0 + tid)*16);
        float4 f0 = __ldg(gp), f1 = __ldg(gp+1), f2 = __ldg(gp+2), f3 = __ldg(gp+3);
        char* row = smem + RS_CAT + tid*432 + 384;
        *(uint4*)(row)      = make_uint4(pack_bf2(f0.x,f0.y), pack_bf2(f0.z,f0.w),
                                         pack_bf2(f1.x,f1.y), pack_bf2(f1.z,f1.w));
        *(uint4*)(row + 16) = make_uint4(pack_bf2(f2.x,f2.y), pack_bf2(f2.z,f2.w),
                                         pack_bf2(f3.x,f3.y), pack_bf2(f3.z,f3.w));
    }
    CP_WAIT(2);
    __syncthreads();

    const uint32_t arow = (uint32_t)(lane & 15), ahalf = (uint32_t)((lane >> 4) * 16);
    const uint32_t brow = (uint32_t)(((lane >> 4) & 1)*8 + (lane & 7));
    const uint32_t bhalf = (uint32_t)(((lane >> 3) & 1) * 16);
    #define ALANE(base, str) ((base) + arow*(str) + ahalf)
    #define WLANE(base, str) ((base) + brow*(str) + bhalf)
    #define OLC(base, str, coff) ((base) + (uint32_t)g*(str) + (uint32_t)t*4 + (coff)), \
                                 ((base) + (uint32_t)(g+8)*(str) + (uint32_t)t*4 + (coff))

    const uint32_t H1p  = su + RS_H1  + pair*16*272;
    const uint32_t H2p  = su + RS_H2  + pair*16*272;
    const uint32_t CATp = su + RS_CAT + pair*16*432;
    const uint32_t Tp   = su + RS_T   + pair*16*144;

    layer<8,8,true>(ALANE(H1p,272), WLANE(su+RS_WD0 + h*64*272, 272), 272,
                    bs+BO_ENC2 + h*64, t, OLC(H2p,272,h*128));
    __syncthreads();
    cpa(su + RS_H1,  (const char*)g_wt + WT_WZ,   17408, tid, 256); CP_COMMIT();
    cpa(su + RS_WD0, (const char*)g_wt + WT_SEL1, 17408, tid, 256); CP_COMMIT();
    CP_WAIT(3);
    __syncthreads();

    layer<8,8,false>(ALANE(H2p,272), WLANE(su+RS_WD1 + h*64*272, 272), 272,
                     bs+BO_Y + h*64, t, OLC(CATp,432,h*128));
    CP_WAIT(1);
    __syncthreads();
    layer<8,4,false>(ALANE(H2p,272), WLANE(su+RS_H1 + h*32*272, 272), 272,
                     bs+BO_Z + h*32, t, OLC(CATp+256,432,h*64));
    __syncthreads();
    cpa(su + RS_WD1, (const char*)g_wt + WT_SEL2, 9216, tid, 256); CP_COMMIT();

    #pragma unroll 1
    for (int cyc = 0; cyc < 3; cyc++){
        layer<13,4,true >(ALANE(CATp,432), WLANE(su+RS_RZ1 + h*32*432, 432), 432,
                          bs+BO_RZ1 + h*32, t, OLC(Tp,144,h*64));
        __syncthreads();
        layer<4, 4,false>(ALANE(Tp,144),   WLANE(su+RS_RZ2 + h*32*144, 144), 144,
                          bs+BO_RZ2 + h*32, t, OLC(CATp+256,432,h*64));
        __syncthreads();
        layer<13,4,true >(ALANE(CATp,432), WLANE(su+RS_RY1 + h*32*432, 432), 432,
                          bs+BO_RY1 + h*32, t, OLC(Tp,144,h*64));
        __syncthreads();
        layer<4, 8,false>(ALANE(Tp,144),   WLANE(su+RS_RY2 + h*64*144, 144), 144,
                          bs+BO_RY2 + h*64, t, OLC(CATp,432,h*128));
        __syncthreads();
    }

    CP_WAIT(1);
    layer<8,4,true>(ALANE(CATp,432), WLANE(su+RS_WD0 + h*32*272, 272), 272,
                    bs+BO_SEL1 + h*32, t, OLC(Tp,144,h*64));
    CP_WAIT(0);
    __syncthreads();

    {
        float acc[4][4];
        initacc<4>(acc, bs + BO_SEL2 + h*32, t);
        gemm<4,4>(acc, ALANE(Tp,144), WLANE(su+RS_WD1 + h*32*144, 144), 144);
        float* LG = (float*)(smem + RS_CAT);
        int r0l = pair*16 + g;
        #pragma unroll
        for (int nt = 0; nt < 4; nt++){
            int c = h*32 + nt*8 + 2*t;
            LG[r0l*64 + c]       = acc[nt][0];
            LG[r0l*64 + c + 1]   = acc[nt][1];
            LG[(r0l+8)*64 + c]   = acc[nt][2];
            LG[(r0l+8)*64 + c+1] = acc[nt][3];
        }
    }
    __syncthreads();
    {
        const float* LG = (const float*)(smem + RS_CAT);
        int r = warp*8 + (lane >> 2);
        int c0 = (lane & 3) * 16;
        int bg = b0 + r;
        float v[16];
        #pragma unroll
        for (int j = 0; j < 16; j += 4){
            float4 gv = *(const float4*)(gum + (size_t)bg*64 + c0 + j);
            v[j]   = LG[r*64 + c0 + j]     + gv.x;
            v[j+1] = LG[r*64 + c0 + j + 1] + gv.y;
            v[j+2] = LG[r*64 + c0 + j + 2] + gv.z;
            v[j+3] = LG[r*64 + c0 + j + 3] + gv.w;
        }
        float m = v[0];
        #pragma unroll
        for (int j = 1; j < 16; j++) m = fmaxf(m, v[j]);
        m = fmaxf(m, __shfl_xor_sync(0xffffffffu, m, 1));
        m = fmaxf(m, __shfl_xor_sync(0xffffffffu, m, 2));
        float s = 0.0f;
        #pragma unroll
        for (int j = 0; j < 16; j++){ v[j] = expf(v[j] - m); s += v[j]; }
        s += __shfl_xor_sync(0xffffffffu, s, 1);
        s += __shfl_xor_sync(0xffffffffu, s, 2);
        float inv = 1.0f / s;
        #pragma unroll
        for (int j = 0; j < 16; j += 4){
            *(float4*)(out + (size_t)bg*64 + c0 + j) =
                make_float4(v[j]*inv, v[j+1]*inv, v[j+2]*inv, v[j+3]*inv);
        }
    }
    #undef ALANE
    #undef WLANE
    #undef OLC
}

/* ---------------------------------------------------------------------- */
extern "C" void kernel_launch(void* const* d_in, const int* in_sizes, int n_in,
                              void* d_out, int out_size){
    const unsigned int* grid32 = (const unsigned int*)d_in[0];
    const float* gfeat  = (const float*)d_in[1];
    const float* gum    = (const float*)d_in[2];
    const float* enc_w1 = (const float*)d_in[3];
    const float* enc_b1 = (const float*)d_in[4];
    const float* enc_w2 = (const float*)d_in[5];
    const float* enc_b2 = (const float*)d_in[6];
    const float* wy     = (const float*)d_in[7];
    const float* by     = (const float*)d_in[8];
    const float* wz     = (const float*)d_in[9];
    const float* bz     = (const float*)d_in[10];
    const float* rz_w1  = (const float*)d_in[11];
    const float* rz_b1  = (const float*)d_in[12];
    const float* rz_w2  = (const float*)d_in[13];
    const float* rz_b2  = (const float*)d_in[14];
    const float* ry_w1  = (const float*)d_in[15];
    const float* ry_b1  = (const float*)d_in[16];
    const float* ry_w2  = (const float*)d_in[17];
    const float* ry_b2  = (const float*)d_in[18];
    const float* sel_w1 = (const float*)d_in[19];
    const float* sel_b1 = (const float*)d_in[20];
    const float* sel_w2 = (const float*)d_in[21];
    const float* sel_b2 = (const float*)d_in[22];
    float* out = (float*)d_out;

    cudaFuncSetAttribute(k_enc1, cudaFuncAttributeMaxDynamicSharedMemorySize, ENC1_SMEM);
    cudaFuncSetAttribute(k_rest, cudaFuncAttributeMaxDynamicSharedMemorySize, RS_TOTAL);

    k_detect<<<1, 32>>>(grid32);
    k_prep<<<2048, 256>>>(enc_w1, grid32, enc_w2, wy, wz, rz_w1, rz_w2, ry_w1, ry_w2, sel_w1, sel_w2);
    k_enc1<<<BB/64, 512, ENC1_SMEM>>>(enc_b1);
    k_rest<<<BB/64, 256, RS_TOTAL>>>(gfeat, gum,
        enc_b2, by, bz, rz_b1, rz_b2, ry_b1, ry_b2, sel_b1, sel_b2, out);
    (void)in_sizes; (void)n_in; (void)out_size;
}